// round 10
// baseline (speedup 1.0000x reference)
#include <cuda_runtime.h>
#include <cfloat>
#include <cstdint>

// ---------------------------------------------------------------------------
// Problem-size constants
// ---------------------------------------------------------------------------
#define N_NODE_MAX 500000
#define N_EDGE_MAX 1000000
#define NREL_MAX   512
#define BATCH_MAX  64

#define SCAN_TPB   256
#define SCAN_EPT   16
#define SCAN_CHUNK 4096
#define NB_MAX     128

// ---------------------------------------------------------------------------
// Device scratch
// ---------------------------------------------------------------------------
__device__ float    g_agg[(size_t)N_NODE_MAX * 64];      // segment-max result
__device__ float    g_node_msg[(size_t)N_NODE_MAX * 64];
__device__ float    g_h5[(size_t)N_NODE_MAX * 8];        // hidden@Ws (padded)
__device__ float    g_alpha[N_EDGE_MAX];
__device__ float    g_s0[N_NODE_MAX];
__device__ float    g_s1[N_NODE_MAX];
__device__ float    g_scores[N_EDGE_MAX];
__device__ float    g_Mext[64 * 66];
__device__ float    g_crel[NREL_MAX * 8];
__device__ float    g_cq[BATCH_MAX * 8];
__device__ unsigned g_max_enc;
__device__ float    g_sum;

// counting-sort scratch (by obj)
__device__ int      g_hist[N_NODE_MAX];
__device__ int      g_off[N_NODE_MAX + 1];
__device__ int      g_cursor[N_NODE_MAX];
__device__ int      g_bsum[NB_MAX];
__device__ int      g_esub[N_EDGE_MAX];
__device__ unsigned g_emeta[N_EDGE_MAX];   // rel | (r_idx<<16)
__device__ int      g_eobj[N_EDGE_MAX];

// counting-sort scratch (by sub)
__device__ int      g_hist2[N_NODE_MAX];
__device__ int      g_off2[N_NODE_MAX + 1];
__device__ int      g_cursor2[N_NODE_MAX];
__device__ int      g_bsum2[NB_MAX];
__device__ int      g2_obj[N_EDGE_MAX];
__device__ int      g2_eidx[N_EDGE_MAX];   // index into obj-sorted arrays

// ---------------------------------------------------------------------------
// Order-preserving float <-> uint encoding
// ---------------------------------------------------------------------------
__device__ __forceinline__ unsigned encf(float x) {
    unsigned u = __float_as_uint(x);
    return (u & 0x80000000u) ? ~u : (u | 0x80000000u);
}
__device__ __forceinline__ float decf(unsigned u) {
    return (u & 0x80000000u) ? __uint_as_float(u & 0x7FFFFFFFu)
                             : __uint_as_float(~u);
}

// ---------------------------------------------------------------------------
// Packed f32x2 helpers
// ---------------------------------------------------------------------------
__device__ __forceinline__ unsigned long long pack2(float a) {
    unsigned long long r;
    asm("mov.b64 %0, {%1, %1};" : "=l"(r) : "r"(__float_as_uint(a)));
    return r;
}
__device__ __forceinline__ void ffma2(unsigned long long& d,
                                      unsigned long long a,
                                      unsigned long long b) {
    asm("fma.rn.f32x2 %0, %1, %2, %0;" : "+l"(d) : "l"(a), "l"(b));
}
__device__ __forceinline__ float2 unpack2(unsigned long long v) {
    unsigned lo, hi;
    asm("mov.b64 {%0, %1}, %2;" : "=r"(lo), "=r"(hi) : "l"(v));
    return make_float2(__uint_as_float(lo), __uint_as_float(hi));
}

// ---------------------------------------------------------------------------
// K0: setup — M_ext = [Wh@Wnode | Wh@w0 | Wh@w1], crel, cq
// ---------------------------------------------------------------------------
__global__ void k_setup(const float* __restrict__ Wh,
                        const float* __restrict__ Wnode,
                        const float* __restrict__ attn_w,
                        const float* __restrict__ rela,
                        const float* __restrict__ Wr,
                        const float* __restrict__ Wqr_w,
                        const float* __restrict__ Wqr_b,
                        const int*   __restrict__ q_rel,
                        int nrel, int batch)
{
    int gtid   = blockIdx.x * blockDim.x + threadIdx.x;
    int stride = gridDim.x * blockDim.x;

    for (int i = gtid; i < 64 * 66; i += stride) {
        int k = i / 66, c = i % 66;
        float s = 0.f;
        if (c < 64) {
            #pragma unroll 8
            for (int j = 0; j < 64; j++) s += Wh[k * 64 + j] * Wnode[j * 64 + c];
        } else {
            const float* w = attn_w + (c - 64) * 64;
            #pragma unroll 8
            for (int j = 0; j < 64; j++) s += Wh[k * 64 + j] * w[j];
        }
        g_Mext[i] = s;
    }
    for (int i = gtid; i < nrel * 5; i += stride) {
        int r = i / 5, j = i % 5;
        float s = 0.f;
        #pragma unroll 8
        for (int k = 0; k < 64; k++) s += rela[r * 64 + k] * Wr[k * 5 + j];
        g_crel[r * 8 + j] = s;
    }
    for (int i = gtid; i < batch * 5; i += stride) {
        int b = i / 5, j = i % 5;
        int qr = q_rel[b];
        float s = Wqr_b[j];
        #pragma unroll 8
        for (int k = 0; k < 64; k++) s += rela[qr * 64 + k] * Wqr_w[k * 5 + j];
        g_cq[b * 8 + j] = s;
    }
}

// ---------------------------------------------------------------------------
// K1: init — hist := 0, hist2 := 0, scalars
// ---------------------------------------------------------------------------
__global__ void k_init(int n_node)
{
    size_t i      = (size_t)blockIdx.x * blockDim.x + threadIdx.x;
    size_t stride = (size_t)gridDim.x * blockDim.x;
    for (size_t t = i; t < (size_t)n_node; t += stride) {
        g_hist[t]  = 0;
        g_hist2[t] = 0;
    }
    if (i == 0) { g_max_enc = 0u; g_sum = 0.f; }
}

// ---------------------------------------------------------------------------
// K2a: histograms over obj AND sub
// ---------------------------------------------------------------------------
__global__ void __launch_bounds__(256)
k_hist(const int* __restrict__ edges, int n_edge)
{
    int e = blockIdx.x * 256 + threadIdx.x;
    if (e < n_edge) {
        int2 so = *reinterpret_cast<const int2*>(edges + (size_t)e * 6 + 4);
        atomicAdd(&g_hist2[so.x], 1);   // sub
        atomicAdd(&g_hist[so.y], 1);    // obj
    }
}

// ---------------------------------------------------------------------------
// K2b/c/d: exclusive scan — `which` selects the array set IN DEVICE CODE
// ---------------------------------------------------------------------------
__global__ void __launch_bounds__(SCAN_TPB)
k_scan_block(int n, int which)
{
    const int* hist = which ? g_hist2 : g_hist;
    int*       off  = which ? g_off2  : g_off;
    int*       bsum = which ? g_bsum2 : g_bsum;

    __shared__ int wsum[8];
    const int tid  = threadIdx.x;
    const int base = blockIdx.x * SCAN_CHUNK + tid * SCAN_EPT;

    int v[SCAN_EPT];
    int s = 0;
    #pragma unroll
    for (int i = 0; i < SCAN_EPT; i++) {
        int idx = base + i;
        v[i] = (idx < n) ? hist[idx] : 0;
        s += v[i];
    }
    const int lane = tid & 31, wid = tid >> 5;
    int inc = s;
    #pragma unroll
    for (int off_ = 1; off_ < 32; off_ <<= 1) {
        int t = __shfl_up_sync(0xFFFFFFFFu, inc, off_);
        if (lane >= off_) inc += t;
    }
    if (lane == 31) wsum[wid] = inc;
    __syncthreads();
    if (wid == 0) {
        int ws = (lane < 8) ? wsum[lane] : 0;
        #pragma unroll
        for (int off_ = 1; off_ < 8; off_ <<= 1) {
            int t = __shfl_up_sync(0xFFFFFFFFu, ws, off_);
            if (lane >= off_) ws += t;
        }
        if (lane < 8) wsum[lane] = ws;
    }
    __syncthreads();
    int run = inc - s + (wid > 0 ? wsum[wid - 1] : 0);
    #pragma unroll
    for (int i = 0; i < SCAN_EPT; i++) {
        int idx = base + i;
        if (idx < n) off[idx] = run;
        run += v[i];
    }
    if (tid == SCAN_TPB - 1) bsum[blockIdx.x] = run;
}

__global__ void k_scan_top(int nb, int which)
{
    int* bsum = which ? g_bsum2 : g_bsum;
    __shared__ int sh[NB_MAX];
    int t = threadIdx.x;
    int v = (t < nb) ? bsum[t] : 0;
    sh[t] = v;
    __syncthreads();
    #pragma unroll
    for (int off = 1; off < NB_MAX; off <<= 1) {
        int a = (t >= off) ? sh[t - off] : 0;
        __syncthreads();
        sh[t] += a;
        __syncthreads();
    }
    if (t < nb) bsum[t] = sh[t] - v;
}

__global__ void k_scan_add(int n, int n_edge, int which)
{
    int*       off    = which ? g_off2    : g_off;
    int*       cursor = which ? g_cursor2 : g_cursor;
    const int* bsum   = which ? g_bsum2   : g_bsum;

    int i = blockIdx.x * 256 + threadIdx.x;
    if (i < n) {
        int o = off[i] + bsum[i >> 12];
        off[i]    = o;
        cursor[i] = o;
    }
    if (i == n) off[n] = n_edge;
}

// ---------------------------------------------------------------------------
// K2e: scatter edges into obj-grouped AND sub-grouped compact arrays
// ---------------------------------------------------------------------------
__global__ void __launch_bounds__(256)
k_scatter(const int* __restrict__ edges, int n_edge)
{
    int e = blockIdx.x * 256 + threadIdx.x;
    if (e >= n_edge) return;
    const int* ep = edges + (size_t)e * 6;
    int r_idx = ep[0];
    int rel   = ep[2];
    int sub   = ep[4];
    int obj   = ep[5];
    int pos = atomicAdd(&g_cursor[obj], 1);
    g_esub[pos]  = sub;
    g_emeta[pos] = (unsigned)rel | ((unsigned)r_idx << 16);
    g_eobj[pos]  = obj;
    int pos2 = atomicAdd(&g_cursor2[sub], 1);
    g2_obj[pos2]  = obj;
    g2_eidx[pos2] = pos;
}

// ---------------------------------------------------------------------------
// K3a: H5 = hidden @ Ws per node (warp per node), padded stride 8
// ---------------------------------------------------------------------------
__global__ void __launch_bounds__(256)
k_h5(const float* __restrict__ hidden,
     const float* __restrict__ Ws,
     int n_node)
{
    const int lane = threadIdx.x & 31;

    float wsa[5], wsb[5];
    #pragma unroll
    for (int j = 0; j < 5; j++) {
        wsa[j] = __ldg(Ws + (2 * lane) * 5 + j);
        wsb[j] = __ldg(Ws + (2 * lane + 1) * 5 + j);
    }

    const int warps_total = gridDim.x * (blockDim.x >> 5);
    int w = blockIdx.x * (blockDim.x >> 5) + (threadIdx.x >> 5);

    for (int node = w; node < n_node; node += warps_total) {
        const float2 h = *reinterpret_cast<const float2*>(hidden + (size_t)node * 64 + 2 * lane);
        float p0 = h.x * wsa[0] + h.y * wsb[0];
        float p1 = h.x * wsa[1] + h.y * wsb[1];
        float p2 = h.x * wsa[2] + h.y * wsb[2];
        float p3 = h.x * wsa[3] + h.y * wsb[3];
        float p4 = h.x * wsa[4] + h.y * wsb[4];
        #pragma unroll
        for (int off = 16; off > 0; off >>= 1) {
            p0 += __shfl_xor_sync(0xFFFFFFFFu, p0, off);
            p1 += __shfl_xor_sync(0xFFFFFFFFu, p1, off);
            p2 += __shfl_xor_sync(0xFFFFFFFFu, p2, off);
            p3 += __shfl_xor_sync(0xFFFFFFFFu, p3, off);
            p4 += __shfl_xor_sync(0xFFFFFFFFu, p4, off);
        }
        if (lane == 0) {
            float* dst = g_h5 + (size_t)node * 8;
            *reinterpret_cast<float4*>(dst) = make_float4(p0, p1, p2, p3);
            dst[4] = p4;
        }
    }
}

// ---------------------------------------------------------------------------
// K3b: alpha per edge (thread per obj-sorted edge)
// ---------------------------------------------------------------------------
__global__ void __launch_bounds__(256)
k_alpha(const float* __restrict__ wa, const float* __restrict__ wab, int n_edge)
{
    const int e = blockIdx.x * 256 + threadIdx.x;
    if (e >= n_edge) return;

    const int      sub  = g_esub[e];
    const unsigned meta = g_emeta[e];
    const int rel   = meta & 0xFFFFu;
    const int r_idx = meta >> 16;

    const float4 h4 = *reinterpret_cast<const float4*>(g_h5 + (size_t)sub * 8);
    const float  h5 = g_h5[(size_t)sub * 8 + 4];
    const float4 c4 = *reinterpret_cast<const float4*>(g_crel + rel * 8);
    const float  c5 = g_crel[rel * 8 + 4];
    const float4 q4 = *reinterpret_cast<const float4*>(g_cq + r_idx * 8);
    const float  q5 = g_cq[r_idx * 8 + 4];

    float z = __ldg(wab);
    z += fmaxf(h4.x + c4.x + q4.x, 0.f) * __ldg(wa + 0);
    z += fmaxf(h4.y + c4.y + q4.y, 0.f) * __ldg(wa + 1);
    z += fmaxf(h4.z + c4.z + q4.z, 0.f) * __ldg(wa + 2);
    z += fmaxf(h4.w + c4.w + q4.w, 0.f) * __ldg(wa + 3);
    z += fmaxf(h5   + c5   + q5,   0.f) * __ldg(wa + 4);
    g_alpha[e] = 1.f / (1.f + expf(-z));
}

// ---------------------------------------------------------------------------
// K3c: segment max — warp per 4 NODES (interleaved edge walks -> MLP 4)
// ---------------------------------------------------------------------------
__global__ void __launch_bounds__(256)
k_edge2(const float* __restrict__ hidden,
        const float* __restrict__ rela,
        int n_node)
{
    const int lane = threadIdx.x & 31;
    const int warps_total = gridDim.x * (blockDim.x >> 5);
    int w = blockIdx.x * (blockDim.x >> 5) + (threadIdx.x >> 5);
    const int n4 = (n_node + 3) >> 2;

    for (int g = w; g < n4; g += warps_total) {
        const int base = g * 4;

        int st[4], en[4];
        #pragma unroll
        for (int q = 0; q < 4; q++) {
            int nd = base + q;
            st[q] = (nd < n_node) ? g_off[nd]     : 0;
            en[q] = (nd < n_node) ? g_off[nd + 1] : 0;
        }
        int mx = 0;
        #pragma unroll
        for (int q = 0; q < 4; q++) mx = max(mx, en[q] - st[q]);

        float m0[4], m1[4];
        #pragma unroll
        for (int q = 0; q < 4; q++) { m0[q] = -FLT_MAX; m1[q] = -FLT_MAX; }

        for (int j = 0; j < mx; j++) {
            #pragma unroll
            for (int q = 0; q < 4; q++) {
                const int i = st[q] + j;
                if (i < en[q]) {
                    const float alpha = __ldg(g_alpha + i);
                    const int   sub   = g_esub[i];
                    const int   rel   = g_emeta[i] & 0xFFFFu;
                    const float2 hs = *reinterpret_cast<const float2*>(
                        hidden + (size_t)sub * 64 + 2 * lane);
                    const float2 hr = *reinterpret_cast<const float2*>(
                        rela + (size_t)rel * 64 + 2 * lane);
                    m0[q] = fmaxf(m0[q], alpha * (hs.x - hr.x));
                    m1[q] = fmaxf(m1[q], alpha * (hs.y - hr.y));
                }
            }
        }

        #pragma unroll
        for (int q = 0; q < 4; q++) {
            int nd = base + q;
            if (nd < n_node) {
                float2 o = (en[q] > st[q]) ? make_float2(m0[q], m1[q])
                                           : make_float2(0.f, 0.f);
                *reinterpret_cast<float2*>(g_agg + (size_t)nd * 64 + 2 * lane) = o;
            }
        }
    }
}

// ---------------------------------------------------------------------------
// K4: node GEMM — 256 rows x 64 cols per block, 256 threads, 8x8 thread tile
// ---------------------------------------------------------------------------
#define AS_STRIDE 68
#define GEMM_ROWS 256
#define GEMM_SMEM ((GEMM_ROWS * AS_STRIDE + 64 * 64 + 128) * 4)

__global__ void __launch_bounds__(256, 2)
k_gemm(int n_node, const float* __restrict__ Wnode_b)
{
    extern __shared__ float smem[];
    float* As  = smem;                            // 256 * 68
    float* MsL = smem + GEMM_ROWS * AS_STRIDE;    // 64 * 64, [k][half][tx][4]
    float* Vs  = MsL + 64 * 64;                   // 64 * 2

    const int tid = threadIdx.x;
    for (int i = tid; i < 64 * 66; i += 256) {
        int k = i / 66, c = i % 66;
        float v = g_Mext[i];
        if (c < 64)
            MsL[k * 64 + ((c & 4) ? 32 : 0) + (c >> 3) * 4 + (c & 3)] = v;
        else
            Vs[k * 2 + (c - 64)] = v;
    }

    const int rb = blockIdx.x * GEMM_ROWS;
    const float4* src = reinterpret_cast<const float4*>(g_agg + (size_t)rb * 64);
    const bool full = (rb + GEMM_ROWS <= n_node);

    #pragma unroll
    for (int t = 0; t < 16; t++) {
        int vidx = tid + t * 256;
        int r  = vidx >> 4;
        int k4 = (vidx & 15) * 4;
        float4 u = make_float4(0.f, 0.f, 0.f, 0.f);
        if (full || rb + r < n_node) u = src[vidx];
        *reinterpret_cast<float4*>(As + r * AS_STRIDE + k4) = u;
    }
    __syncthreads();

    const int tx = tid & 7;
    const int ty = tid >> 3;

    unsigned long long acc[8][4];
    #pragma unroll
    for (int i = 0; i < 8; i++)
        #pragma unroll
        for (int c = 0; c < 4; c++) acc[i][c] = 0ull;

    const float* arow  = As + ty * 8 * AS_STRIDE;
    const float* mbase = MsL + tx * 4;

    for (int k4 = 0; k4 < 64; k4 += 4) {
        float4 a[8];
        #pragma unroll
        for (int i = 0; i < 8; i++)
            a[i] = *reinterpret_cast<const float4*>(arow + i * AS_STRIDE + k4);

        #pragma unroll
        for (int kk = 0; kk < 4; kk++) {
            const ulonglong2 mp0 = *reinterpret_cast<const ulonglong2*>(mbase + (k4 + kk) * 64);
            const ulonglong2 mp1 = *reinterpret_cast<const ulonglong2*>(mbase + (k4 + kk) * 64 + 32);
            #pragma unroll
            for (int i = 0; i < 8; i++) {
                const float av = (kk == 0) ? a[i].x : (kk == 1) ? a[i].y
                               : (kk == 2) ? a[i].z : a[i].w;
                const unsigned long long aa = pack2(av);
                ffma2(acc[i][0], aa, mp0.x);
                ffma2(acc[i][1], aa, mp0.y);
                ffma2(acc[i][2], aa, mp1.x);
                ffma2(acc[i][3], aa, mp1.y);
            }
        }
    }

    const float4 b0 = *reinterpret_cast<const float4*>(Wnode_b + tx * 8);
    const float4 b1 = *reinterpret_cast<const float4*>(Wnode_b + tx * 8 + 4);
    #pragma unroll
    for (int i = 0; i < 8; i++) {
        int grow = rb + ty * 8 + i;
        if (grow < n_node) {
            float2 a0 = unpack2(acc[i][0]);
            float2 a1 = unpack2(acc[i][1]);
            float2 a2 = unpack2(acc[i][2]);
            float2 a3 = unpack2(acc[i][3]);
            float* op = g_node_msg + (size_t)grow * 64 + tx * 8;
            *reinterpret_cast<float4*>(op) =
                make_float4(a0.x + b0.x, a0.y + b0.y, a1.x + b0.z, a1.y + b0.w);
            *reinterpret_cast<float4*>(op + 4) =
                make_float4(a2.x + b1.x, a2.y + b1.y, a3.x + b1.z, a3.y + b1.w);
        }
    }

    // s0/s1 epilogue: one row per thread
    {
        int grow = rb + tid;
        if (grow < n_node) {
            unsigned long long s01 = 0ull;
            const float* ar = As + tid * AS_STRIDE;
            #pragma unroll 8
            for (int k = 0; k < 64; k++) {
                const unsigned long long v01 =
                    *reinterpret_cast<const unsigned long long*>(Vs + k * 2);
                ffma2(s01, pack2(ar[k]), v01);
            }
            float2 s = unpack2(s01);
            g_s0[grow] = s.x;
            g_s1[grow] = s.y;
        }
    }
}

// ---------------------------------------------------------------------------
// K5: edge scores + global max
// ---------------------------------------------------------------------------
__global__ void __launch_bounds__(256)
k_score(const float* __restrict__ attn_b, int n_edge)
{
    const int e = blockIdx.x * 256 + threadIdx.x;
    float sc = -FLT_MAX;
    if (e < n_edge) {
        float s = g_s0[g_esub[e]] + g_s1[g_eobj[e]] + __ldg(attn_b);
        sc = (s > 0.f) ? s : 0.2f * s;
        g_scores[e] = sc;
    }
    __shared__ float red[8];
    const int lane = threadIdx.x & 31, wid = threadIdx.x >> 5;
    #pragma unroll
    for (int off = 16; off > 0; off >>= 1)
        sc = fmaxf(sc, __shfl_xor_sync(0xFFFFFFFFu, sc, off));
    if (lane == 0) red[wid] = sc;
    __syncthreads();
    if (wid == 0) {
        float v = (lane < 8) ? red[lane] : -FLT_MAX;
        #pragma unroll
        for (int off = 4; off > 0; off >>= 1)
            v = fmaxf(v, __shfl_xor_sync(0xFFFFFFFFu, v, off));
        if (lane == 0) atomicMax(&g_max_enc, encf(v));
    }
}

// ---------------------------------------------------------------------------
// K6: exp(score - max) in place + global sum
// ---------------------------------------------------------------------------
__global__ void __launch_bounds__(256)
k_expsum(int n_edge)
{
    const float gm = decf(g_max_enc);
    const int e = blockIdx.x * 256 + threadIdx.x;
    float v = 0.f;
    if (e < n_edge) {
        v = expf(g_scores[e] - gm);
        g_scores[e] = v;
    }
    __shared__ float red[8];
    const int lane = threadIdx.x & 31, wid = threadIdx.x >> 5;
    #pragma unroll
    for (int off = 16; off > 0; off >>= 1)
        v += __shfl_xor_sync(0xFFFFFFFFu, v, off);
    if (lane == 0) red[wid] = v;
    __syncthreads();
    if (wid == 0) {
        float s = (lane < 8) ? red[lane] : 0.f;
        #pragma unroll
        for (int off = 4; off > 0; off >>= 1)
            s += __shfl_xor_sync(0xFFFFFFFFu, s, off);
        if (lane == 0) atomicAdd(&g_sum, s);
    }
}

// ---------------------------------------------------------------------------
// K7: final gather — warp per 4 NODES (interleaved edge walks -> MLP 4)
// ---------------------------------------------------------------------------
__global__ void __launch_bounds__(256)
k_final(float* __restrict__ out, int n_node)
{
    const float inv = 1.f / g_sum;
    const int lane = threadIdx.x & 31;
    const int warps_total = gridDim.x * (blockDim.x >> 5);
    int w = blockIdx.x * (blockDim.x >> 5) + (threadIdx.x >> 5);
    const int n4 = (n_node + 3) >> 2;

    for (int g = w; g < n4; g += warps_total) {
        const int base = g * 4;

        int st[4], en[4];
        #pragma unroll
        for (int q = 0; q < 4; q++) {
            int nd = base + q;
            st[q] = (nd < n_node) ? g_off2[nd]     : 0;
            en[q] = (nd < n_node) ? g_off2[nd + 1] : 0;
        }
        int mx = 0;
        #pragma unroll
        for (int q = 0; q < 4; q++) mx = max(mx, en[q] - st[q]);

        float a0[4], a1[4];
        #pragma unroll
        for (int q = 0; q < 4; q++) { a0[q] = 0.f; a1[q] = 0.f; }

        for (int j = 0; j < mx; j++) {
            #pragma unroll
            for (int q = 0; q < 4; q++) {
                const int i = st[q] + j;
                if (i < en[q]) {
                    const int   obj = g2_obj[i];
                    const float wgt = __ldg(g_scores + g2_eidx[i]) * inv;
                    const float2 m = *reinterpret_cast<const float2*>(
                        g_node_msg + (size_t)obj * 64 + 2 * lane);
                    a0[q] += wgt * m.x;
                    a1[q] += wgt * m.y;
                }
            }
        }

        #pragma unroll
        for (int q = 0; q < 4; q++) {
            int nd = base + q;
            if (nd < n_node)
                *reinterpret_cast<float2*>(out + (size_t)nd * 64 + 2 * lane) =
                    make_float2(a0[q], a1[q]);
        }
    }
}

// ---------------------------------------------------------------------------
// kernel_launch
// ---------------------------------------------------------------------------
extern "C" void kernel_launch(void* const* d_in, const int* in_sizes, int n_in,
                              void* d_out, int out_size)
{
    const float* hidden    = (const float*)d_in[0];
    const float* rela      = (const float*)d_in[1];
    const float* Ws        = (const float*)d_in[2];
    const float* Wr        = (const float*)d_in[3];
    const float* Wqr_w     = (const float*)d_in[4];
    const float* Wqr_b     = (const float*)d_in[5];
    const float* walpha_w  = (const float*)d_in[6];
    const float* walpha_b  = (const float*)d_in[7];
    const float* Wh        = (const float*)d_in[8];
    const float* attn_fc_w = (const float*)d_in[9];
    const float* attn_fc_b = (const float*)d_in[10];
    const float* Wnode_w   = (const float*)d_in[11];
    const float* Wnode_b   = (const float*)d_in[12];
    const int*   q_rel     = (const int*)d_in[14];
    const int*   edges     = (const int*)d_in[15];
    float*       out       = (float*)d_out;

    const int n_edge = in_sizes[15] / 6;
    const int n_node = in_sizes[16] / 2;
    const int nrel   = in_sizes[1] / 64;
    const int batch  = in_sizes[14];
    const int nb     = (n_node + SCAN_CHUNK - 1) / SCAN_CHUNK;

    static bool attr_set = false;
    if (!attr_set) {
        cudaFuncSetAttribute(k_gemm, cudaFuncAttributeMaxDynamicSharedMemorySize,
                             GEMM_SMEM);
        attr_set = true;
    }

    // small tables
    k_setup<<<32, 256>>>(Wh, Wnode_w, attn_fc_w, rela, Wr, Wqr_w, Wqr_b,
                         q_rel, nrel, batch);

    // init hists + scalars
    k_init<<<2048, 256>>>(n_node);

    // dual counting sort (by obj and by sub)
    k_hist<<<(n_edge + 255) / 256, 256>>>(edges, n_edge);
    k_scan_block<<<nb, SCAN_TPB>>>(n_node, 0);
    k_scan_top<<<1, NB_MAX>>>(nb, 0);
    k_scan_add<<<(n_node + 256) / 256, 256>>>(n_node, n_edge, 0);
    k_scan_block<<<nb, SCAN_TPB>>>(n_node, 1);
    k_scan_top<<<1, NB_MAX>>>(nb, 1);
    k_scan_add<<<(n_node + 256) / 256, 256>>>(n_node, n_edge, 1);
    k_scatter<<<(n_edge + 255) / 256, 256>>>(edges, n_edge);

    // attention precompute
    k_h5<<<2368, 256>>>(hidden, Ws, n_node);
    k_alpha<<<(n_edge + 255) / 256, 256>>>(walpha_w, walpha_b, n_edge);

    // segment max (4-node interleaved, high MLP)
    k_edge2<<<2368, 256>>>(hidden, rela, n_node);

    // node GEMM (8x8 thread tile)
    k_gemm<<<(n_node + GEMM_ROWS - 1) / GEMM_ROWS, 256, GEMM_SMEM>>>(n_node, Wnode_b);

    // softmax statistics
    k_score<<<(n_edge + 255) / 256, 256>>>(attn_fc_b, n_edge);
    k_expsum<<<(n_edge + 255) / 256, 256>>>(n_edge);

    // final gather (4-node interleaved, no atomics)
    k_final<<<2368, 256>>>(out, n_node);
}

// round 11
// speedup vs baseline: 1.0639x; 1.0639x over previous
#include <cuda_runtime.h>
#include <cfloat>
#include <cstdint>

// ---------------------------------------------------------------------------
// Problem-size constants
// ---------------------------------------------------------------------------
#define N_NODE_MAX 500000
#define N_EDGE_MAX 1000000
#define NREL_MAX   512
#define BATCH_MAX  64

#define SCAN_TPB   256
#define SCAN_EPT   16
#define SCAN_CHUNK 4096
#define NB_MAX     128

// ---------------------------------------------------------------------------
// Device scratch
// ---------------------------------------------------------------------------
__device__ float    g_agg[(size_t)N_NODE_MAX * 64];      // segment-max result
__device__ float    g_node_msg[(size_t)N_NODE_MAX * 64];
__device__ float    g_h5[(size_t)N_NODE_MAX * 8];        // hidden@Ws (padded)
__device__ float    g_alpha[N_EDGE_MAX];
__device__ float    g_s0[N_NODE_MAX];
__device__ float    g_s1[N_NODE_MAX];
__device__ float    g_scores[N_EDGE_MAX];
__device__ float    g_Mext[64 * 66];
__device__ float    g_crel[NREL_MAX * 8];
__device__ float    g_cq[BATCH_MAX * 8];
__device__ unsigned g_max_enc;
__device__ float    g_sum;

// counting-sort scratch (by obj)
__device__ int      g_hist[N_NODE_MAX];
__device__ int      g_off[N_NODE_MAX + 1];
__device__ int      g_cursor[N_NODE_MAX];
__device__ int      g_bsum[NB_MAX];
__device__ int      g_esub[N_EDGE_MAX];
__device__ unsigned g_emeta[N_EDGE_MAX];   // rel | (r_idx<<16)
__device__ int      g_eobj[N_EDGE_MAX];

// counting-sort scratch (by sub)
__device__ int      g_hist2[N_NODE_MAX];
__device__ int      g_off2[N_NODE_MAX + 1];
__device__ int      g_cursor2[N_NODE_MAX];
__device__ int      g_bsum2[NB_MAX];
__device__ int      g2_obj[N_EDGE_MAX];
__device__ int      g2_eidx[N_EDGE_MAX];   // index into obj-sorted arrays

// ---------------------------------------------------------------------------
// Order-preserving float <-> uint encoding
// ---------------------------------------------------------------------------
__device__ __forceinline__ unsigned encf(float x) {
    unsigned u = __float_as_uint(x);
    return (u & 0x80000000u) ? ~u : (u | 0x80000000u);
}
__device__ __forceinline__ float decf(unsigned u) {
    return (u & 0x80000000u) ? __uint_as_float(u & 0x7FFFFFFFu)
                             : __uint_as_float(~u);
}

// ---------------------------------------------------------------------------
// Packed f32x2 helpers
// ---------------------------------------------------------------------------
__device__ __forceinline__ unsigned long long pack2(float a) {
    unsigned long long r;
    asm("mov.b64 %0, {%1, %1};" : "=l"(r) : "r"(__float_as_uint(a)));
    return r;
}
__device__ __forceinline__ void ffma2(unsigned long long& d,
                                      unsigned long long a,
                                      unsigned long long b) {
    asm("fma.rn.f32x2 %0, %1, %2, %0;" : "+l"(d) : "l"(a), "l"(b));
}
__device__ __forceinline__ float2 unpack2(unsigned long long v) {
    unsigned lo, hi;
    asm("mov.b64 {%0, %1}, %2;" : "=r"(lo), "=r"(hi) : "l"(v));
    return make_float2(__uint_as_float(lo), __uint_as_float(hi));
}

// ---------------------------------------------------------------------------
// K0: setup — M_ext = [Wh@Wnode | Wh@w0 | Wh@w1], crel, cq
// ---------------------------------------------------------------------------
__global__ void k_setup(const float* __restrict__ Wh,
                        const float* __restrict__ Wnode,
                        const float* __restrict__ attn_w,
                        const float* __restrict__ rela,
                        const float* __restrict__ Wr,
                        const float* __restrict__ Wqr_w,
                        const float* __restrict__ Wqr_b,
                        const int*   __restrict__ q_rel,
                        int nrel, int batch)
{
    int gtid   = blockIdx.x * blockDim.x + threadIdx.x;
    int stride = gridDim.x * blockDim.x;

    for (int i = gtid; i < 64 * 66; i += stride) {
        int k = i / 66, c = i % 66;
        float s = 0.f;
        if (c < 64) {
            #pragma unroll 8
            for (int j = 0; j < 64; j++) s += Wh[k * 64 + j] * Wnode[j * 64 + c];
        } else {
            const float* w = attn_w + (c - 64) * 64;
            #pragma unroll 8
            for (int j = 0; j < 64; j++) s += Wh[k * 64 + j] * w[j];
        }
        g_Mext[i] = s;
    }
    for (int i = gtid; i < nrel * 5; i += stride) {
        int r = i / 5, j = i % 5;
        float s = 0.f;
        #pragma unroll 8
        for (int k = 0; k < 64; k++) s += rela[r * 64 + k] * Wr[k * 5 + j];
        g_crel[r * 8 + j] = s;
    }
    for (int i = gtid; i < batch * 5; i += stride) {
        int b = i / 5, j = i % 5;
        int qr = q_rel[b];
        float s = Wqr_b[j];
        #pragma unroll 8
        for (int k = 0; k < 64; k++) s += rela[qr * 64 + k] * Wqr_w[k * 5 + j];
        g_cq[b * 8 + j] = s;
    }
}

// ---------------------------------------------------------------------------
// K1: init — hist := 0, hist2 := 0, scalars
// ---------------------------------------------------------------------------
__global__ void k_init(int n_node)
{
    size_t i      = (size_t)blockIdx.x * blockDim.x + threadIdx.x;
    size_t stride = (size_t)gridDim.x * blockDim.x;
    for (size_t t = i; t < (size_t)n_node; t += stride) {
        g_hist[t]  = 0;
        g_hist2[t] = 0;
    }
    if (i == 0) { g_max_enc = 0u; g_sum = 0.f; }
}

// ---------------------------------------------------------------------------
// K2a: histograms over obj AND sub
// ---------------------------------------------------------------------------
__global__ void __launch_bounds__(256)
k_hist(const int* __restrict__ edges, int n_edge)
{
    int e = blockIdx.x * 256 + threadIdx.x;
    if (e < n_edge) {
        int2 so = *reinterpret_cast<const int2*>(edges + (size_t)e * 6 + 4);
        atomicAdd(&g_hist2[so.x], 1);   // sub
        atomicAdd(&g_hist[so.y], 1);    // obj
    }
}

// ---------------------------------------------------------------------------
// K2b/c/d: exclusive scan — ONE launch covers both sorts (blockIdx selects)
// ---------------------------------------------------------------------------
__global__ void __launch_bounds__(SCAN_TPB)
k_scan_block(int n, int nb)
{
    const int which = (blockIdx.x >= nb);
    const int bid   = which ? (blockIdx.x - nb) : blockIdx.x;
    const int* hist = which ? g_hist2 : g_hist;
    int*       off  = which ? g_off2  : g_off;
    int*       bsum = which ? g_bsum2 : g_bsum;

    __shared__ int wsum[8];
    const int tid  = threadIdx.x;
    const int base = bid * SCAN_CHUNK + tid * SCAN_EPT;

    int v[SCAN_EPT];
    int s = 0;
    #pragma unroll
    for (int i = 0; i < SCAN_EPT; i++) {
        int idx = base + i;
        v[i] = (idx < n) ? hist[idx] : 0;
        s += v[i];
    }
    const int lane = tid & 31, wid = tid >> 5;
    int inc = s;
    #pragma unroll
    for (int off_ = 1; off_ < 32; off_ <<= 1) {
        int t = __shfl_up_sync(0xFFFFFFFFu, inc, off_);
        if (lane >= off_) inc += t;
    }
    if (lane == 31) wsum[wid] = inc;
    __syncthreads();
    if (wid == 0) {
        int ws = (lane < 8) ? wsum[lane] : 0;
        #pragma unroll
        for (int off_ = 1; off_ < 8; off_ <<= 1) {
            int t = __shfl_up_sync(0xFFFFFFFFu, ws, off_);
            if (lane >= off_) ws += t;
        }
        if (lane < 8) wsum[lane] = ws;
    }
    __syncthreads();
    int run = inc - s + (wid > 0 ? wsum[wid - 1] : 0);
    #pragma unroll
    for (int i = 0; i < SCAN_EPT; i++) {
        int idx = base + i;
        if (idx < n) off[idx] = run;
        run += v[i];
    }
    if (tid == SCAN_TPB - 1) bsum[bid] = run;
}

__global__ void k_scan_top(int nb)
{
    int* bsum = blockIdx.x ? g_bsum2 : g_bsum;
    __shared__ int sh[NB_MAX];
    int t = threadIdx.x;
    int v = (t < nb) ? bsum[t] : 0;
    sh[t] = v;
    __syncthreads();
    #pragma unroll
    for (int off = 1; off < NB_MAX; off <<= 1) {
        int a = (t >= off) ? sh[t - off] : 0;
        __syncthreads();
        sh[t] += a;
        __syncthreads();
    }
    if (t < nb) bsum[t] = sh[t] - v;
}

__global__ void k_scan_add(int n, int n_edge, int nba)
{
    const int which = (blockIdx.x >= nba);
    const int bid   = which ? (blockIdx.x - nba) : blockIdx.x;
    int*       off    = which ? g_off2    : g_off;
    int*       cursor = which ? g_cursor2 : g_cursor;
    const int* bsum   = which ? g_bsum2   : g_bsum;

    int i = bid * 256 + threadIdx.x;
    if (i < n) {
        int o = off[i] + bsum[i >> 12];
        off[i]    = o;
        cursor[i] = o;
    }
    if (i == n) off[n] = n_edge;
}

// ---------------------------------------------------------------------------
// K2e: scatter edges into obj-grouped AND sub-grouped compact arrays
// ---------------------------------------------------------------------------
__global__ void __launch_bounds__(256)
k_scatter(const int* __restrict__ edges, int n_edge)
{
    int e = blockIdx.x * 256 + threadIdx.x;
    if (e >= n_edge) return;
    const int* ep = edges + (size_t)e * 6;
    int r_idx = ep[0];
    int rel   = ep[2];
    int sub   = ep[4];
    int obj   = ep[5];
    int pos = atomicAdd(&g_cursor[obj], 1);
    g_esub[pos]  = sub;
    g_emeta[pos] = (unsigned)rel | ((unsigned)r_idx << 16);
    g_eobj[pos]  = obj;
    int pos2 = atomicAdd(&g_cursor2[sub], 1);
    g2_obj[pos2]  = obj;
    g2_eidx[pos2] = pos;
}

// ---------------------------------------------------------------------------
// K3a: H5 = hidden @ Ws per node (warp per node), padded stride 8
// ---------------------------------------------------------------------------
__global__ void __launch_bounds__(256)
k_h5(const float* __restrict__ hidden,
     const float* __restrict__ Ws,
     int n_node)
{
    const int lane = threadIdx.x & 31;

    float wsa[5], wsb[5];
    #pragma unroll
    for (int j = 0; j < 5; j++) {
        wsa[j] = __ldg(Ws + (2 * lane) * 5 + j);
        wsb[j] = __ldg(Ws + (2 * lane + 1) * 5 + j);
    }

    const int warps_total = gridDim.x * (blockDim.x >> 5);
    int w = blockIdx.x * (blockDim.x >> 5) + (threadIdx.x >> 5);

    for (int node = w; node < n_node; node += warps_total) {
        const float2 h = *reinterpret_cast<const float2*>(hidden + (size_t)node * 64 + 2 * lane);
        float p0 = h.x * wsa[0] + h.y * wsb[0];
        float p1 = h.x * wsa[1] + h.y * wsb[1];
        float p2 = h.x * wsa[2] + h.y * wsb[2];
        float p3 = h.x * wsa[3] + h.y * wsb[3];
        float p4 = h.x * wsa[4] + h.y * wsb[4];
        #pragma unroll
        for (int off = 16; off > 0; off >>= 1) {
            p0 += __shfl_xor_sync(0xFFFFFFFFu, p0, off);
            p1 += __shfl_xor_sync(0xFFFFFFFFu, p1, off);
            p2 += __shfl_xor_sync(0xFFFFFFFFu, p2, off);
            p3 += __shfl_xor_sync(0xFFFFFFFFu, p3, off);
            p4 += __shfl_xor_sync(0xFFFFFFFFu, p4, off);
        }
        if (lane == 0) {
            float* dst = g_h5 + (size_t)node * 8;
            *reinterpret_cast<float4*>(dst) = make_float4(p0, p1, p2, p3);
            dst[4] = p4;
        }
    }
}

// ---------------------------------------------------------------------------
// K3b: alpha per edge (thread per obj-sorted edge)
// ---------------------------------------------------------------------------
__global__ void __launch_bounds__(256)
k_alpha(const float* __restrict__ wa, const float* __restrict__ wab, int n_edge)
{
    const int e = blockIdx.x * 256 + threadIdx.x;
    if (e >= n_edge) return;

    const int      sub  = g_esub[e];
    const unsigned meta = g_emeta[e];
    const int rel   = meta & 0xFFFFu;
    const int r_idx = meta >> 16;

    const float4 h4 = *reinterpret_cast<const float4*>(g_h5 + (size_t)sub * 8);
    const float  h5 = g_h5[(size_t)sub * 8 + 4];
    const float4 c4 = *reinterpret_cast<const float4*>(g_crel + rel * 8);
    const float  c5 = g_crel[rel * 8 + 4];
    const float4 q4 = *reinterpret_cast<const float4*>(g_cq + r_idx * 8);
    const float  q5 = g_cq[r_idx * 8 + 4];

    float z = __ldg(wab);
    z += fmaxf(h4.x + c4.x + q4.x, 0.f) * __ldg(wa + 0);
    z += fmaxf(h4.y + c4.y + q4.y, 0.f) * __ldg(wa + 1);
    z += fmaxf(h4.z + c4.z + q4.z, 0.f) * __ldg(wa + 2);
    z += fmaxf(h4.w + c4.w + q4.w, 0.f) * __ldg(wa + 3);
    z += fmaxf(h5   + c5   + q5,   0.f) * __ldg(wa + 4);
    g_alpha[e] = 1.f / (1.f + expf(-z));
}

// ---------------------------------------------------------------------------
// K3c: segment max — warp per node, node's own edges processed in PAIRS
//      (4 concurrent gathers, no predication waste)
// ---------------------------------------------------------------------------
__global__ void __launch_bounds__(256)
k_edge2(const float* __restrict__ hidden,
        const float* __restrict__ rela,
        int n_node)
{
    const int lane = threadIdx.x & 31;
    const int warps_total = gridDim.x * (blockDim.x >> 5);
    int w = blockIdx.x * (blockDim.x >> 5) + (threadIdx.x >> 5);

    for (int node = w; node < n_node; node += warps_total) {
        const int start = g_off[node];
        const int end   = g_off[node + 1];

        float m0 = -FLT_MAX, m1 = -FLT_MAX;
        int i = start;
        for (; i + 1 < end; i += 2) {
            const float alA = __ldg(g_alpha + i);
            const float alB = __ldg(g_alpha + i + 1);
            const int   subA = g_esub[i],            subB = g_esub[i + 1];
            const int   relA = g_emeta[i] & 0xFFFFu, relB = g_emeta[i + 1] & 0xFFFFu;
            const float2 hsA = *reinterpret_cast<const float2*>(hidden + (size_t)subA * 64 + 2 * lane);
            const float2 hsB = *reinterpret_cast<const float2*>(hidden + (size_t)subB * 64 + 2 * lane);
            const float2 hrA = *reinterpret_cast<const float2*>(rela   + (size_t)relA * 64 + 2 * lane);
            const float2 hrB = *reinterpret_cast<const float2*>(rela   + (size_t)relB * 64 + 2 * lane);
            m0 = fmaxf(m0, alA * (hsA.x - hrA.x));
            m1 = fmaxf(m1, alA * (hsA.y - hrA.y));
            m0 = fmaxf(m0, alB * (hsB.x - hrB.x));
            m1 = fmaxf(m1, alB * (hsB.y - hrB.y));
        }
        if (i < end) {
            const float alpha = __ldg(g_alpha + i);
            const int   sub   = g_esub[i];
            const int   rel   = g_emeta[i] & 0xFFFFu;
            const float2 hs = *reinterpret_cast<const float2*>(hidden + (size_t)sub * 64 + 2 * lane);
            const float2 hr = *reinterpret_cast<const float2*>(rela   + (size_t)rel * 64 + 2 * lane);
            m0 = fmaxf(m0, alpha * (hs.x - hr.x));
            m1 = fmaxf(m1, alpha * (hs.y - hr.y));
        }
        float2 o = (end > start) ? make_float2(m0, m1) : make_float2(0.f, 0.f);
        *reinterpret_cast<float2*>(g_agg + (size_t)node * 64 + 2 * lane) = o;
    }
}

// ---------------------------------------------------------------------------
// K4: node GEMM — 256 rows x 64 cols per block, 256 threads, 8x8 thread tile
// ---------------------------------------------------------------------------
#define AS_STRIDE 68
#define GEMM_ROWS 256
#define GEMM_SMEM ((GEMM_ROWS * AS_STRIDE + 64 * 64 + 128) * 4)

__global__ void __launch_bounds__(256, 2)
k_gemm(int n_node, const float* __restrict__ Wnode_b)
{
    extern __shared__ float smem[];
    float* As  = smem;                            // 256 * 68
    float* MsL = smem + GEMM_ROWS * AS_STRIDE;    // 64 * 64, [k][half][tx][4]
    float* Vs  = MsL + 64 * 64;                   // 64 * 2

    const int tid = threadIdx.x;
    for (int i = tid; i < 64 * 66; i += 256) {
        int k = i / 66, c = i % 66;
        float v = g_Mext[i];
        if (c < 64)
            MsL[k * 64 + ((c & 4) ? 32 : 0) + (c >> 3) * 4 + (c & 3)] = v;
        else
            Vs[k * 2 + (c - 64)] = v;
    }

    const int rb = blockIdx.x * GEMM_ROWS;
    const float4* src = reinterpret_cast<const float4*>(g_agg + (size_t)rb * 64);
    const bool full = (rb + GEMM_ROWS <= n_node);

    #pragma unroll
    for (int t = 0; t < 16; t++) {
        int vidx = tid + t * 256;
        int r  = vidx >> 4;
        int k4 = (vidx & 15) * 4;
        float4 u = make_float4(0.f, 0.f, 0.f, 0.f);
        if (full || rb + r < n_node) u = src[vidx];
        *reinterpret_cast<float4*>(As + r * AS_STRIDE + k4) = u;
    }
    __syncthreads();

    const int tx = tid & 7;
    const int ty = tid >> 3;

    unsigned long long acc[8][4];
    #pragma unroll
    for (int i = 0; i < 8; i++)
        #pragma unroll
        for (int c = 0; c < 4; c++) acc[i][c] = 0ull;

    const float* arow  = As + ty * 8 * AS_STRIDE;
    const float* mbase = MsL + tx * 4;

    for (int k4 = 0; k4 < 64; k4 += 4) {
        float4 a[8];
        #pragma unroll
        for (int i = 0; i < 8; i++)
            a[i] = *reinterpret_cast<const float4*>(arow + i * AS_STRIDE + k4);

        #pragma unroll
        for (int kk = 0; kk < 4; kk++) {
            const ulonglong2 mp0 = *reinterpret_cast<const ulonglong2*>(mbase + (k4 + kk) * 64);
            const ulonglong2 mp1 = *reinterpret_cast<const ulonglong2*>(mbase + (k4 + kk) * 64 + 32);
            #pragma unroll
            for (int i = 0; i < 8; i++) {
                const float av = (kk == 0) ? a[i].x : (kk == 1) ? a[i].y
                               : (kk == 2) ? a[i].z : a[i].w;
                const unsigned long long aa = pack2(av);
                ffma2(acc[i][0], aa, mp0.x);
                ffma2(acc[i][1], aa, mp0.y);
                ffma2(acc[i][2], aa, mp1.x);
                ffma2(acc[i][3], aa, mp1.y);
            }
        }
    }

    const float4 b0 = *reinterpret_cast<const float4*>(Wnode_b + tx * 8);
    const float4 b1 = *reinterpret_cast<const float4*>(Wnode_b + tx * 8 + 4);
    #pragma unroll
    for (int i = 0; i < 8; i++) {
        int grow = rb + ty * 8 + i;
        if (grow < n_node) {
            float2 a0 = unpack2(acc[i][0]);
            float2 a1 = unpack2(acc[i][1]);
            float2 a2 = unpack2(acc[i][2]);
            float2 a3 = unpack2(acc[i][3]);
            float* op = g_node_msg + (size_t)grow * 64 + tx * 8;
            *reinterpret_cast<float4*>(op) =
                make_float4(a0.x + b0.x, a0.y + b0.y, a1.x + b0.z, a1.y + b0.w);
            *reinterpret_cast<float4*>(op + 4) =
                make_float4(a2.x + b1.x, a2.y + b1.y, a3.x + b1.z, a3.y + b1.w);
        }
    }

    // s0/s1 epilogue: one row per thread
    {
        int grow = rb + tid;
        if (grow < n_node) {
            unsigned long long s01 = 0ull;
            const float* ar = As + tid * AS_STRIDE;
            #pragma unroll 8
            for (int k = 0; k < 64; k++) {
                const unsigned long long v01 =
                    *reinterpret_cast<const unsigned long long*>(Vs + k * 2);
                ffma2(s01, pack2(ar[k]), v01);
            }
            float2 s = unpack2(s01);
            g_s0[grow] = s.x;
            g_s1[grow] = s.y;
        }
    }
}

// ---------------------------------------------------------------------------
// K5: edge scores + global max
// ---------------------------------------------------------------------------
__global__ void __launch_bounds__(256)
k_score(const float* __restrict__ attn_b, int n_edge)
{
    const int e = blockIdx.x * 256 + threadIdx.x;
    float sc = -FLT_MAX;
    if (e < n_edge) {
        float s = g_s0[g_esub[e]] + g_s1[g_eobj[e]] + __ldg(attn_b);
        sc = (s > 0.f) ? s : 0.2f * s;
        g_scores[e] = sc;
    }
    __shared__ float red[8];
    const int lane = threadIdx.x & 31, wid = threadIdx.x >> 5;
    #pragma unroll
    for (int off = 16; off > 0; off >>= 1)
        sc = fmaxf(sc, __shfl_xor_sync(0xFFFFFFFFu, sc, off));
    if (lane == 0) red[wid] = sc;
    __syncthreads();
    if (wid == 0) {
        float v = (lane < 8) ? red[lane] : -FLT_MAX;
        #pragma unroll
        for (int off = 4; off > 0; off >>= 1)
            v = fmaxf(v, __shfl_xor_sync(0xFFFFFFFFu, v, off));
        if (lane == 0) atomicMax(&g_max_enc, encf(v));
    }
}

// ---------------------------------------------------------------------------
// K6: global sum of exp(score - max) — no exp store (k_final recomputes)
// ---------------------------------------------------------------------------
__global__ void __launch_bounds__(256)
k_sum(int n_edge)
{
    const float gm = decf(g_max_enc);
    const int e = blockIdx.x * 256 + threadIdx.x;
    float v = 0.f;
    if (e < n_edge) v = expf(g_scores[e] - gm);
    __shared__ float red[8];
    const int lane = threadIdx.x & 31, wid = threadIdx.x >> 5;
    #pragma unroll
    for (int off = 16; off > 0; off >>= 1)
        v += __shfl_xor_sync(0xFFFFFFFFu, v, off);
    if (lane == 0) red[wid] = v;
    __syncthreads();
    if (wid == 0) {
        float s = (lane < 8) ? red[lane] : 0.f;
        #pragma unroll
        for (int off = 4; off > 0; off >>= 1)
            s += __shfl_xor_sync(0xFFFFFFFFu, s, off);
        if (lane == 0) atomicAdd(&g_sum, s);
    }
}

// ---------------------------------------------------------------------------
// K7: final gather — warp per node, edges in PAIRS; exp recomputed inline
// ---------------------------------------------------------------------------
__global__ void __launch_bounds__(256)
k_final(float* __restrict__ out, int n_node)
{
    const float inv = 1.f / g_sum;
    const float gm  = decf(g_max_enc);
    const int lane = threadIdx.x & 31;
    const int warps_total = gridDim.x * (blockDim.x >> 5);
    int w = blockIdx.x * (blockDim.x >> 5) + (threadIdx.x >> 5);

    for (int node = w; node < n_node; node += warps_total) {
        const int start = g_off2[node];
        const int end   = g_off2[node + 1];

        float a0 = 0.f, a1 = 0.f;
        int i = start;
        for (; i + 1 < end; i += 2) {
            const int objA = g2_obj[i],   objB = g2_obj[i + 1];
            const float scA = __ldg(g_scores + g2_eidx[i]);
            const float scB = __ldg(g_scores + g2_eidx[i + 1]);
            const float2 mA = *reinterpret_cast<const float2*>(
                g_node_msg + (size_t)objA * 64 + 2 * lane);
            const float2 mB = *reinterpret_cast<const float2*>(
                g_node_msg + (size_t)objB * 64 + 2 * lane);
            const float wA = expf(scA - gm) * inv;
            const float wB = expf(scB - gm) * inv;
            a0 += wA * mA.x + wB * mB.x;
            a1 += wA * mA.y + wB * mB.y;
        }
        if (i < end) {
            const int   obj = g2_obj[i];
            const float sc  = __ldg(g_scores + g2_eidx[i]);
            const float2 m = *reinterpret_cast<const float2*>(
                g_node_msg + (size_t)obj * 64 + 2 * lane);
            const float wgt = expf(sc - gm) * inv;
            a0 += wgt * m.x;
            a1 += wgt * m.y;
        }
        *reinterpret_cast<float2*>(out + (size_t)node * 64 + 2 * lane) =
            make_float2(a0, a1);
    }
}

// ---------------------------------------------------------------------------
// kernel_launch
// ---------------------------------------------------------------------------
extern "C" void kernel_launch(void* const* d_in, const int* in_sizes, int n_in,
                              void* d_out, int out_size)
{
    const float* hidden    = (const float*)d_in[0];
    const float* rela      = (const float*)d_in[1];
    const float* Ws        = (const float*)d_in[2];
    const float* Wr        = (const float*)d_in[3];
    const float* Wqr_w     = (const float*)d_in[4];
    const float* Wqr_b     = (const float*)d_in[5];
    const float* walpha_w  = (const float*)d_in[6];
    const float* walpha_b  = (const float*)d_in[7];
    const float* Wh        = (const float*)d_in[8];
    const float* attn_fc_w = (const float*)d_in[9];
    const float* attn_fc_b = (const float*)d_in[10];
    const float* Wnode_w   = (const float*)d_in[11];
    const float* Wnode_b   = (const float*)d_in[12];
    const int*   q_rel     = (const int*)d_in[14];
    const int*   edges     = (const int*)d_in[15];
    float*       out       = (float*)d_out;

    const int n_edge = in_sizes[15] / 6;
    const int n_node = in_sizes[16] / 2;
    const int nrel   = in_sizes[1] / 64;
    const int batch  = in_sizes[14];
    const int nb     = (n_node + SCAN_CHUNK - 1) / SCAN_CHUNK;
    const int nba    = (n_node + 256) / 256;   // covers n_node+1 entries

    static bool attr_set = false;
    if (!attr_set) {
        cudaFuncSetAttribute(k_gemm, cudaFuncAttributeMaxDynamicSharedMemorySize,
                             GEMM_SMEM);
        attr_set = true;
    }

    // small tables
    k_setup<<<32, 256>>>(Wh, Wnode_w, attn_fc_w, rela, Wr, Wqr_w, Wqr_b,
                         q_rel, nrel, batch);

    // init hists + scalars
    k_init<<<2048, 256>>>(n_node);

    // dual counting sort (by obj and by sub) — merged scan launches
    k_hist<<<(n_edge + 255) / 256, 256>>>(edges, n_edge);
    k_scan_block<<<2 * nb, SCAN_TPB>>>(n_node, nb);
    k_scan_top<<<2, NB_MAX>>>(nb);
    k_scan_add<<<2 * nba, 256>>>(n_node, n_edge, nba);
    k_scatter<<<(n_edge + 255) / 256, 256>>>(edges, n_edge);

    // attention precompute
    k_h5<<<2368, 256>>>(hidden, Ws, n_node);
    k_alpha<<<(n_edge + 255) / 256, 256>>>(walpha_w, walpha_b, n_edge);

    // segment max (serial per node, paired edges)
    k_edge2<<<2368, 256>>>(hidden, rela, n_node);

    // node GEMM (8x8 thread tile)
    k_gemm<<<(n_node + GEMM_ROWS - 1) / GEMM_ROWS, 256, GEMM_SMEM>>>(n_node, Wnode_b);

    // softmax statistics
    k_score<<<(n_edge + 255) / 256, 256>>>(attn_fc_b, n_edge);
    k_sum<<<(n_edge + 255) / 256, 256>>>(n_edge);

    // final gather (serial per node, paired edges, exp inline)
    k_final<<<2368, 256>>>(out, n_node);
}

// round 12
// speedup vs baseline: 1.1064x; 1.0399x over previous
#include <cuda_runtime.h>
#include <cfloat>
#include <cstdint>

// ---------------------------------------------------------------------------
// Problem-size constants
// ---------------------------------------------------------------------------
#define N_NODE_MAX 500000
#define N_EDGE_MAX 1000000
#define NREL_MAX   512
#define BATCH_MAX  64

#define SCAN_TPB   256
#define SCAN_EPT   16
#define SCAN_CHUNK 4096
#define NB_MAX     128

// ---------------------------------------------------------------------------
// Device scratch
// ---------------------------------------------------------------------------
__device__ float    g_agg[(size_t)N_NODE_MAX * 64];      // segment-max result
__device__ float    g_node_msg[(size_t)N_NODE_MAX * 64];
__device__ float    g_h5[(size_t)N_NODE_MAX * 8];        // hidden@Ws (padded)
__device__ float    g_alpha[N_EDGE_MAX];
__device__ float    g_s0[N_NODE_MAX];
__device__ float    g_s1[N_NODE_MAX];
__device__ float    g_scores[N_EDGE_MAX];
__device__ float    g_Mext[64 * 66];
__device__ float    g_crel[NREL_MAX * 8];
__device__ float    g_cq[BATCH_MAX * 8];
__device__ unsigned g_max_enc;
__device__ float    g_sum;

// counting-sort scratch (by obj)
__device__ int      g_hist[N_NODE_MAX];
__device__ int      g_off[N_NODE_MAX + 1];
__device__ int      g_cursor[N_NODE_MAX];
__device__ int      g_bsum[NB_MAX];
__device__ int      g_esub[N_EDGE_MAX];
__device__ int      g_erel[N_EDGE_MAX];
__device__ int      g_eobj[N_EDGE_MAX];

// ---------------------------------------------------------------------------
// Order-preserving float <-> uint encoding
// ---------------------------------------------------------------------------
__device__ __forceinline__ unsigned encf(float x) {
    unsigned u = __float_as_uint(x);
    return (u & 0x80000000u) ? ~u : (u | 0x80000000u);
}
__device__ __forceinline__ float decf(unsigned u) {
    return (u & 0x80000000u) ? __uint_as_float(u & 0x7FFFFFFFu)
                             : __uint_as_float(~u);
}

// ---------------------------------------------------------------------------
// Packed f32x2 helpers
// ---------------------------------------------------------------------------
__device__ __forceinline__ unsigned long long pack2(float a) {
    unsigned long long r;
    asm("mov.b64 %0, {%1, %1};" : "=l"(r) : "r"(__float_as_uint(a)));
    return r;
}
__device__ __forceinline__ void ffma2(unsigned long long& d,
                                      unsigned long long a,
                                      unsigned long long b) {
    asm("fma.rn.f32x2 %0, %1, %2, %0;" : "+l"(d) : "l"(a), "l"(b));
}
__device__ __forceinline__ float2 unpack2(unsigned long long v) {
    unsigned lo, hi;
    asm("mov.b64 {%0, %1}, %2;" : "=r"(lo), "=r"(hi) : "l"(v));
    return make_float2(__uint_as_float(lo), __uint_as_float(hi));
}

// ---------------------------------------------------------------------------
// K0: setup — M_ext = [Wh@Wnode | Wh@w0 | Wh@w1], crel, cq
// ---------------------------------------------------------------------------
__global__ void k_setup(const float* __restrict__ Wh,
                        const float* __restrict__ Wnode,
                        const float* __restrict__ attn_w,
                        const float* __restrict__ rela,
                        const float* __restrict__ Wr,
                        const float* __restrict__ Wqr_w,
                        const float* __restrict__ Wqr_b,
                        const int*   __restrict__ q_rel,
                        int nrel, int batch)
{
    int gtid   = blockIdx.x * blockDim.x + threadIdx.x;
    int stride = gridDim.x * blockDim.x;

    for (int i = gtid; i < 64 * 66; i += stride) {
        int k = i / 66, c = i % 66;
        float s = 0.f;
        if (c < 64) {
            #pragma unroll 8
            for (int j = 0; j < 64; j++) s += Wh[k * 64 + j] * Wnode[j * 64 + c];
        } else {
            const float* w = attn_w + (c - 64) * 64;
            #pragma unroll 8
            for (int j = 0; j < 64; j++) s += Wh[k * 64 + j] * w[j];
        }
        g_Mext[i] = s;
    }
    for (int i = gtid; i < nrel * 5; i += stride) {
        int r = i / 5, j = i % 5;
        float s = 0.f;
        #pragma unroll 8
        for (int k = 0; k < 64; k++) s += rela[r * 64 + k] * Wr[k * 5 + j];
        g_crel[r * 8 + j] = s;
    }
    for (int i = gtid; i < batch * 5; i += stride) {
        int b = i / 5, j = i % 5;
        int qr = q_rel[b];
        float s = Wqr_b[j];
        #pragma unroll 8
        for (int k = 0; k < 64; k++) s += rela[qr * 64 + k] * Wqr_w[k * 5 + j];
        g_cq[b * 8 + j] = s;
    }
}

// ---------------------------------------------------------------------------
// K1: init — out := 0, hist := 0, scalars
// ---------------------------------------------------------------------------
__global__ void k_init(float* __restrict__ out, int out_elems, int n_node)
{
    size_t i      = (size_t)blockIdx.x * blockDim.x + threadIdx.x;
    size_t stride = (size_t)gridDim.x * blockDim.x;

    float4* op = reinterpret_cast<float4*>(out);
    size_t  no = (size_t)out_elems >> 2;
    float4  zv = make_float4(0.f, 0.f, 0.f, 0.f);
    for (size_t t = i; t < no; t += stride) op[t] = zv;

    for (size_t t = i; t < (size_t)n_node; t += stride) g_hist[t] = 0;
    if (i == 0) { g_max_enc = 0u; g_sum = 0.f; }
}

// ---------------------------------------------------------------------------
// K2a: histogram over obj
// ---------------------------------------------------------------------------
__global__ void __launch_bounds__(256)
k_hist(const int* __restrict__ edges, int n_edge)
{
    int e = blockIdx.x * 256 + threadIdx.x;
    if (e < n_edge) atomicAdd(&g_hist[edges[(size_t)e * 6 + 5]], 1);
}

// ---------------------------------------------------------------------------
// K2b/c/d: exclusive scan of g_hist -> g_off (+cursor copy)
// ---------------------------------------------------------------------------
__global__ void __launch_bounds__(SCAN_TPB)
k_scan_block(int n)
{
    __shared__ int wsum[8];
    const int tid  = threadIdx.x;
    const int base = blockIdx.x * SCAN_CHUNK + tid * SCAN_EPT;

    int v[SCAN_EPT];
    int s = 0;
    #pragma unroll
    for (int i = 0; i < SCAN_EPT; i++) {
        int idx = base + i;
        v[i] = (idx < n) ? g_hist[idx] : 0;
        s += v[i];
    }
    const int lane = tid & 31, wid = tid >> 5;
    int inc = s;
    #pragma unroll
    for (int off_ = 1; off_ < 32; off_ <<= 1) {
        int t = __shfl_up_sync(0xFFFFFFFFu, inc, off_);
        if (lane >= off_) inc += t;
    }
    if (lane == 31) wsum[wid] = inc;
    __syncthreads();
    if (wid == 0) {
        int ws = (lane < 8) ? wsum[lane] : 0;
        #pragma unroll
        for (int off_ = 1; off_ < 8; off_ <<= 1) {
            int t = __shfl_up_sync(0xFFFFFFFFu, ws, off_);
            if (lane >= off_) ws += t;
        }
        if (lane < 8) wsum[lane] = ws;
    }
    __syncthreads();
    int run = inc - s + (wid > 0 ? wsum[wid - 1] : 0);
    #pragma unroll
    for (int i = 0; i < SCAN_EPT; i++) {
        int idx = base + i;
        if (idx < n) g_off[idx] = run;
        run += v[i];
    }
    if (tid == SCAN_TPB - 1) g_bsum[blockIdx.x] = run;
}

__global__ void k_scan_top(int nb)
{
    __shared__ int sh[NB_MAX];
    int t = threadIdx.x;
    int v = (t < nb) ? g_bsum[t] : 0;
    sh[t] = v;
    __syncthreads();
    #pragma unroll
    for (int off = 1; off < NB_MAX; off <<= 1) {
        int a = (t >= off) ? sh[t - off] : 0;
        __syncthreads();
        sh[t] += a;
        __syncthreads();
    }
    if (t < nb) g_bsum[t] = sh[t] - v;
}

__global__ void k_scan_add(int n, int n_edge)
{
    int i = blockIdx.x * 256 + threadIdx.x;
    if (i < n) {
        int o = g_off[i] + g_bsum[i >> 12];
        g_off[i]    = o;
        g_cursor[i] = o;
    }
    if (i == n) g_off[n] = n_edge;
}

// ---------------------------------------------------------------------------
// K3a: H5 = hidden @ Ws per node (warp per node) — runs BEFORE the scatter
// ---------------------------------------------------------------------------
__global__ void __launch_bounds__(256)
k_h5(const float* __restrict__ hidden,
     const float* __restrict__ Ws,
     int n_node)
{
    const int lane = threadIdx.x & 31;

    float wsa[5], wsb[5];
    #pragma unroll
    for (int j = 0; j < 5; j++) {
        wsa[j] = __ldg(Ws + (2 * lane) * 5 + j);
        wsb[j] = __ldg(Ws + (2 * lane + 1) * 5 + j);
    }

    const int warps_total = gridDim.x * (blockDim.x >> 5);
    int w = blockIdx.x * (blockDim.x >> 5) + (threadIdx.x >> 5);

    for (int node = w; node < n_node; node += warps_total) {
        const float2 h = *reinterpret_cast<const float2*>(hidden + (size_t)node * 64 + 2 * lane);
        float p0 = h.x * wsa[0] + h.y * wsb[0];
        float p1 = h.x * wsa[1] + h.y * wsb[1];
        float p2 = h.x * wsa[2] + h.y * wsb[2];
        float p3 = h.x * wsa[3] + h.y * wsb[3];
        float p4 = h.x * wsa[4] + h.y * wsb[4];
        #pragma unroll
        for (int off = 16; off > 0; off >>= 1) {
            p0 += __shfl_xor_sync(0xFFFFFFFFu, p0, off);
            p1 += __shfl_xor_sync(0xFFFFFFFFu, p1, off);
            p2 += __shfl_xor_sync(0xFFFFFFFFu, p2, off);
            p3 += __shfl_xor_sync(0xFFFFFFFFu, p3, off);
            p4 += __shfl_xor_sync(0xFFFFFFFFu, p4, off);
        }
        if (lane == 0) {
            float* dst = g_h5 + (size_t)node * 8;
            *reinterpret_cast<float4*>(dst) = make_float4(p0, p1, p2, p3);
            dst[4] = p4;
        }
    }
}

// ---------------------------------------------------------------------------
// K2e: scatter edges into obj-grouped arrays + alpha computed inline
//      (folds the former k_alpha pass: one less full-edge sweep)
// ---------------------------------------------------------------------------
__global__ void __launch_bounds__(256)
k_scatter(const int* __restrict__ edges,
          const float* __restrict__ wa, const float* __restrict__ wab,
          int n_edge)
{
    int e = blockIdx.x * 256 + threadIdx.x;
    if (e >= n_edge) return;
    const int* ep = edges + (size_t)e * 6;
    int r_idx = ep[0];
    int rel   = ep[2];
    int sub   = ep[4];
    int obj   = ep[5];

    int pos = atomicAdd(&g_cursor[obj], 1);
    g_esub[pos] = sub;
    g_erel[pos] = rel;
    g_eobj[pos] = obj;

    // alpha = sigmoid(relu(h5[sub] + crel[rel] + cq[r_idx]) . wa + b)
    const float4 h4 = *reinterpret_cast<const float4*>(g_h5 + (size_t)sub * 8);
    const float  h5 = g_h5[(size_t)sub * 8 + 4];
    const float4 c4 = *reinterpret_cast<const float4*>(g_crel + rel * 8);
    const float  c5 = g_crel[rel * 8 + 4];
    const float4 q4 = *reinterpret_cast<const float4*>(g_cq + r_idx * 8);
    const float  q5 = g_cq[r_idx * 8 + 4];

    float z = __ldg(wab);
    z += fmaxf(h4.x + c4.x + q4.x, 0.f) * __ldg(wa + 0);
    z += fmaxf(h4.y + c4.y + q4.y, 0.f) * __ldg(wa + 1);
    z += fmaxf(h4.z + c4.z + q4.z, 0.f) * __ldg(wa + 2);
    z += fmaxf(h4.w + c4.w + q4.w, 0.f) * __ldg(wa + 3);
    z += fmaxf(h5   + c5   + q5,   0.f) * __ldg(wa + 4);
    g_alpha[pos] = 1.f / (1.f + expf(-z));
}

// ---------------------------------------------------------------------------
// K3c: segment max — warp per node, serial edge walk (Round-6 form)
// ---------------------------------------------------------------------------
__global__ void __launch_bounds__(256)
k_edge2(const float* __restrict__ hidden,
        const float* __restrict__ rela,
        int n_node)
{
    const int lane = threadIdx.x & 31;
    const int warps_total = gridDim.x * (blockDim.x >> 5);
    int w = blockIdx.x * (blockDim.x >> 5) + (threadIdx.x >> 5);

    for (int node = w; node < n_node; node += warps_total) {
        const int start = g_off[node];
        const int end   = g_off[node + 1];

        float m0 = -FLT_MAX, m1 = -FLT_MAX;
        for (int i = start; i < end; i++) {
            const float alpha = __ldg(g_alpha + i);
            const int   sub   = g_esub[i];
            const int   rel   = g_erel[i];
            const float2 hs = *reinterpret_cast<const float2*>(hidden + (size_t)sub * 64 + 2 * lane);
            const float2 hr = *reinterpret_cast<const float2*>(rela   + (size_t)rel * 64 + 2 * lane);
            m0 = fmaxf(m0, alpha * (hs.x - hr.x));
            m1 = fmaxf(m1, alpha * (hs.y - hr.y));
        }
        float2 o = (end > start) ? make_float2(m0, m1) : make_float2(0.f, 0.f);
        *reinterpret_cast<float2*>(g_agg + (size_t)node * 64 + 2 * lane) = o;
    }
}

// ---------------------------------------------------------------------------
// K4: node GEMM — 256 rows x 64 cols per block, 256 threads, 8x8 thread tile
// ---------------------------------------------------------------------------
#define AS_STRIDE 68
#define GEMM_ROWS 256
#define GEMM_SMEM ((GEMM_ROWS * AS_STRIDE + 64 * 64 + 128) * 4)

__global__ void __launch_bounds__(256, 2)
k_gemm(int n_node, const float* __restrict__ Wnode_b)
{
    extern __shared__ float smem[];
    float* As  = smem;                            // 256 * 68
    float* MsL = smem + GEMM_ROWS * AS_STRIDE;    // 64 * 64, [k][half][tx][4]
    float* Vs  = MsL + 64 * 64;                   // 64 * 2

    const int tid = threadIdx.x;
    for (int i = tid; i < 64 * 66; i += 256) {
        int k = i / 66, c = i % 66;
        float v = g_Mext[i];
        if (c < 64)
            MsL[k * 64 + ((c & 4) ? 32 : 0) + (c >> 3) * 4 + (c & 3)] = v;
        else
            Vs[k * 2 + (c - 64)] = v;
    }

    const int rb = blockIdx.x * GEMM_ROWS;
    const float4* src = reinterpret_cast<const float4*>(g_agg + (size_t)rb * 64);
    const bool full = (rb + GEMM_ROWS <= n_node);

    #pragma unroll
    for (int t = 0; t < 16; t++) {
        int vidx = tid + t * 256;
        int r  = vidx >> 4;
        int k4 = (vidx & 15) * 4;
        float4 u = make_float4(0.f, 0.f, 0.f, 0.f);
        if (full || rb + r < n_node) u = src[vidx];
        *reinterpret_cast<float4*>(As + r * AS_STRIDE + k4) = u;
    }
    __syncthreads();

    const int tx = tid & 7;
    const int ty = tid >> 3;

    unsigned long long acc[8][4];
    #pragma unroll
    for (int i = 0; i < 8; i++)
        #pragma unroll
        for (int c = 0; c < 4; c++) acc[i][c] = 0ull;

    const float* arow  = As + ty * 8 * AS_STRIDE;
    const float* mbase = MsL + tx * 4;

    for (int k4 = 0; k4 < 64; k4 += 4) {
        float4 a[8];
        #pragma unroll
        for (int i = 0; i < 8; i++)
            a[i] = *reinterpret_cast<const float4*>(arow + i * AS_STRIDE + k4);

        #pragma unroll
        for (int kk = 0; kk < 4; kk++) {
            const ulonglong2 mp0 = *reinterpret_cast<const ulonglong2*>(mbase + (k4 + kk) * 64);
            const ulonglong2 mp1 = *reinterpret_cast<const ulonglong2*>(mbase + (k4 + kk) * 64 + 32);
            #pragma unroll
            for (int i = 0; i < 8; i++) {
                const float av = (kk == 0) ? a[i].x : (kk == 1) ? a[i].y
                               : (kk == 2) ? a[i].z : a[i].w;
                const unsigned long long aa = pack2(av);
                ffma2(acc[i][0], aa, mp0.x);
                ffma2(acc[i][1], aa, mp0.y);
                ffma2(acc[i][2], aa, mp1.x);
                ffma2(acc[i][3], aa, mp1.y);
            }
        }
    }

    const float4 b0 = *reinterpret_cast<const float4*>(Wnode_b + tx * 8);
    const float4 b1 = *reinterpret_cast<const float4*>(Wnode_b + tx * 8 + 4);
    #pragma unroll
    for (int i = 0; i < 8; i++) {
        int grow = rb + ty * 8 + i;
        if (grow < n_node) {
            float2 a0 = unpack2(acc[i][0]);
            float2 a1 = unpack2(acc[i][1]);
            float2 a2 = unpack2(acc[i][2]);
            float2 a3 = unpack2(acc[i][3]);
            float* op = g_node_msg + (size_t)grow * 64 + tx * 8;
            *reinterpret_cast<float4*>(op) =
                make_float4(a0.x + b0.x, a0.y + b0.y, a1.x + b0.z, a1.y + b0.w);
            *reinterpret_cast<float4*>(op + 4) =
                make_float4(a2.x + b1.x, a2.y + b1.y, a3.x + b1.z, a3.y + b1.w);
        }
    }

    // s0/s1 epilogue: one row per thread
    {
        int grow = rb + tid;
        if (grow < n_node) {
            unsigned long long s01 = 0ull;
            const float* ar = As + tid * AS_STRIDE;
            #pragma unroll 8
            for (int k = 0; k < 64; k++) {
                const unsigned long long v01 =
                    *reinterpret_cast<const unsigned long long*>(Vs + k * 2);
                ffma2(s01, pack2(ar[k]), v01);
            }
            float2 s = unpack2(s01);
            g_s0[grow] = s.x;
            g_s1[grow] = s.y;
        }
    }
}

// ---------------------------------------------------------------------------
// K5: edge scores + global max
// ---------------------------------------------------------------------------
__global__ void __launch_bounds__(256)
k_score(const float* __restrict__ attn_b, int n_edge)
{
    const int e = blockIdx.x * 256 + threadIdx.x;
    float sc = -FLT_MAX;
    if (e < n_edge) {
        float s = g_s0[g_esub[e]] + g_s1[g_eobj[e]] + __ldg(attn_b);
        sc = (s > 0.f) ? s : 0.2f * s;
        g_scores[e] = sc;
    }
    __shared__ float red[8];
    const int lane = threadIdx.x & 31, wid = threadIdx.x >> 5;
    #pragma unroll
    for (int off = 16; off > 0; off >>= 1)
        sc = fmaxf(sc, __shfl_xor_sync(0xFFFFFFFFu, sc, off));
    if (lane == 0) red[wid] = sc;
    __syncthreads();
    if (wid == 0) {
        float v = (lane < 8) ? red[lane] : -FLT_MAX;
        #pragma unroll
        for (int off = 4; off > 0; off >>= 1)
            v = fmaxf(v, __shfl_xor_sync(0xFFFFFFFFu, v, off));
        if (lane == 0) atomicMax(&g_max_enc, encf(v));
    }
}

// ---------------------------------------------------------------------------
// K6: exp(score - max) in place + global sum
// ---------------------------------------------------------------------------
__global__ void __launch_bounds__(256)
k_expsum(int n_edge)
{
    const float gm = decf(g_max_enc);
    const int e = blockIdx.x * 256 + threadIdx.x;
    float v = 0.f;
    if (e < n_edge) {
        v = expf(g_scores[e] - gm);
        g_scores[e] = v;
    }
    __shared__ float red[8];
    const int lane = threadIdx.x & 31, wid = threadIdx.x >> 5;
    #pragma unroll
    for (int off = 16; off > 0; off >>= 1)
        v += __shfl_xor_sync(0xFFFFFFFFu, v, off);
    if (lane == 0) red[wid] = v;
    __syncthreads();
    if (wid == 0) {
        float s = (lane < 8) ? red[lane] : 0.f;
        #pragma unroll
        for (int off = 4; off > 0; off >>= 1)
            s += __shfl_xor_sync(0xFFFFFFFFu, s, off);
        if (lane == 0) atomicAdd(&g_sum, s);
    }
}

// ---------------------------------------------------------------------------
// K7: final weighted scatter — out[sub] += w_e * node_msg[obj]
//     16 threads per edge, vectorized red.global.add.v4.f32 (Round-6 form)
// ---------------------------------------------------------------------------
__global__ void __launch_bounds__(256)
k_final(float* __restrict__ out, int n_edge)
{
    const float inv = 1.f / g_sum;
    const int t = blockIdx.x * 256 + threadIdx.x;
    const int e = t >> 4;
    const int q = t & 15;
    if (e >= n_edge) return;

    const int sub = g_esub[e];
    const int obj = g_eobj[e];
    const float wgt = g_scores[e] * inv;
    const float4 m = *reinterpret_cast<const float4*>(
        g_node_msg + (size_t)obj * 64 + q * 4);
    float* op = out + (size_t)sub * 64 + q * 4;
    asm volatile("red.global.add.v4.f32 [%0], {%1, %2, %3, %4};"
                 :: "l"(op), "f"(wgt * m.x), "f"(wgt * m.y),
                    "f"(wgt * m.z), "f"(wgt * m.w)
                 : "memory");
}

// ---------------------------------------------------------------------------
// kernel_launch
// ---------------------------------------------------------------------------
extern "C" void kernel_launch(void* const* d_in, const int* in_sizes, int n_in,
                              void* d_out, int out_size)
{
    const float* hidden    = (const float*)d_in[0];
    const float* rela      = (const float*)d_in[1];
    const float* Ws        = (const float*)d_in[2];
    const float* Wr        = (const float*)d_in[3];
    const float* Wqr_w     = (const float*)d_in[4];
    const float* Wqr_b     = (const float*)d_in[5];
    const float* walpha_w  = (const float*)d_in[6];
    const float* walpha_b  = (const float*)d_in[7];
    const float* Wh        = (const float*)d_in[8];
    const float* attn_fc_w = (const float*)d_in[9];
    const float* attn_fc_b = (const float*)d_in[10];
    const float* Wnode_w   = (const float*)d_in[11];
    const float* Wnode_b   = (const float*)d_in[12];
    const int*   q_rel     = (const int*)d_in[14];
    const int*   edges     = (const int*)d_in[15];
    float*       out       = (float*)d_out;

    const int n_edge = in_sizes[15] / 6;
    const int n_node = in_sizes[16] / 2;
    const int nrel   = in_sizes[1] / 64;
    const int batch  = in_sizes[14];
    const int nb     = (n_node + SCAN_CHUNK - 1) / SCAN_CHUNK;

    static bool attr_set = false;
    if (!attr_set) {
        cudaFuncSetAttribute(k_gemm, cudaFuncAttributeMaxDynamicSharedMemorySize,
                             GEMM_SMEM);
        attr_set = true;
    }

    // small tables
    k_setup<<<32, 256>>>(Wh, Wnode_w, attn_fc_w, rela, Wr, Wqr_w, Wqr_b,
                         q_rel, nrel, batch);

    // init out + hist + scalars
    k_init<<<4096, 256>>>(out, out_size, n_node);

    // H5 precompute (independent of the sort; must precede k_scatter)
    k_h5<<<2368, 256>>>(hidden, Ws, n_node);

    // counting sort of edges by obj (+alpha computed inside the scatter)
    k_hist<<<(n_edge + 255) / 256, 256>>>(edges, n_edge);
    k_scan_block<<<nb, SCAN_TPB>>>(n_node);
    k_scan_top<<<1, NB_MAX>>>(nb);
    k_scan_add<<<(n_node + 256) / 256, 256>>>(n_node, n_edge);
    k_scatter<<<(n_edge + 255) / 256, 256>>>(edges, walpha_w, walpha_b, n_edge);

    // segment max (serial per node, high occupancy)
    k_edge2<<<2368, 256>>>(hidden, rela, n_node);

    // node GEMM (8x8 thread tile)
    k_gemm<<<(n_node + GEMM_ROWS - 1) / GEMM_ROWS, 256, GEMM_SMEM>>>(n_node, Wnode_b);

    // softmax statistics
    k_score<<<(n_edge + 255) / 256, 256>>>(attn_fc_b, n_edge);
    k_expsum<<<(n_edge + 255) / 256, 256>>>(n_edge);

    // weighted scatter to output (16 threads/edge, RED.128)
    k_final<<<(n_edge * 16 + 255) / 256, 256>>>(out, n_edge);
}

// round 13
// speedup vs baseline: 1.1225x; 1.0146x over previous
#include <cuda_runtime.h>
#include <cfloat>
#include <cstdint>

// ---------------------------------------------------------------------------
// Problem-size constants
// ---------------------------------------------------------------------------
#define N_NODE_MAX 500000
#define N_EDGE_MAX 1000000
#define NREL_MAX   512
#define BATCH_MAX  64

#define SCAN_TPB   256
#define SCAN_EPT   16
#define SCAN_CHUNK 4096
#define NB_MAX     128

// ---------------------------------------------------------------------------
// Device scratch
// ---------------------------------------------------------------------------
__device__ float    g_agg[(size_t)N_NODE_MAX * 64];      // segment-max result
__device__ float    g_t[(size_t)N_NODE_MAX * 64];        // sum_e w_e * agg[obj_e]
__device__ float    g_wsum[N_NODE_MAX];                  // sum_e w_e (per sub)
__device__ float    g_h5[(size_t)N_NODE_MAX * 8];        // hidden@Ws (padded)
__device__ float    g_alpha[N_EDGE_MAX];
__device__ float    g_s0[N_NODE_MAX];
__device__ float    g_s1[N_NODE_MAX];
__device__ float    g_scores[N_EDGE_MAX];
__device__ float    g_Mext[64 * 66];                     // [k][c]: c<64 M, 64 v0, 65 v1
__device__ float    g_crel[NREL_MAX * 8];
__device__ float    g_cq[BATCH_MAX * 8];
__device__ unsigned g_max_enc;
__device__ float    g_sum;

// counting-sort scratch (by obj)
__device__ int      g_hist[N_NODE_MAX];
__device__ int      g_off[N_NODE_MAX + 1];
__device__ int      g_cursor[N_NODE_MAX];
__device__ int      g_bsum[NB_MAX];
__device__ int      g_esub[N_EDGE_MAX];
__device__ int      g_erel[N_EDGE_MAX];
__device__ int      g_eobj[N_EDGE_MAX];

// ---------------------------------------------------------------------------
// Order-preserving float <-> uint encoding
// ---------------------------------------------------------------------------
__device__ __forceinline__ unsigned encf(float x) {
    unsigned u = __float_as_uint(x);
    return (u & 0x80000000u) ? ~u : (u | 0x80000000u);
}
__device__ __forceinline__ float decf(unsigned u) {
    return (u & 0x80000000u) ? __uint_as_float(u & 0x7FFFFFFFu)
                             : __uint_as_float(~u);
}

// ---------------------------------------------------------------------------
// Packed f32x2 helpers
// ---------------------------------------------------------------------------
__device__ __forceinline__ unsigned long long pack2(float a) {
    unsigned long long r;
    asm("mov.b64 %0, {%1, %1};" : "=l"(r) : "r"(__float_as_uint(a)));
    return r;
}
__device__ __forceinline__ void ffma2(unsigned long long& d,
                                      unsigned long long a,
                                      unsigned long long b) {
    asm("fma.rn.f32x2 %0, %1, %2, %0;" : "+l"(d) : "l"(a), "l"(b));
}
__device__ __forceinline__ float2 unpack2(unsigned long long v) {
    unsigned lo, hi;
    asm("mov.b64 {%0, %1}, %2;" : "=r"(lo), "=r"(hi) : "l"(v));
    return make_float2(__uint_as_float(lo), __uint_as_float(hi));
}

// ---------------------------------------------------------------------------
// K0: setup — M_ext = [Wh@Wnode | Wh@w0 | Wh@w1], crel, cq
// ---------------------------------------------------------------------------
__global__ void k_setup(const float* __restrict__ Wh,
                        const float* __restrict__ Wnode,
                        const float* __restrict__ attn_w,
                        const float* __restrict__ rela,
                        const float* __restrict__ Wr,
                        const float* __restrict__ Wqr_w,
                        const float* __restrict__ Wqr_b,
                        const int*   __restrict__ q_rel,
                        int nrel, int batch)
{
    int gtid   = blockIdx.x * blockDim.x + threadIdx.x;
    int stride = gridDim.x * blockDim.x;

    for (int i = gtid; i < 64 * 66; i += stride) {
        int k = i / 66, c = i % 66;
        float s = 0.f;
        if (c < 64) {
            #pragma unroll 8
            for (int j = 0; j < 64; j++) s += Wh[k * 64 + j] * Wnode[j * 64 + c];
        } else {
            const float* w = attn_w + (c - 64) * 64;
            #pragma unroll 8
            for (int j = 0; j < 64; j++) s += Wh[k * 64 + j] * w[j];
        }
        g_Mext[i] = s;
    }
    for (int i = gtid; i < nrel * 5; i += stride) {
        int r = i / 5, j = i % 5;
        float s = 0.f;
        #pragma unroll 8
        for (int k = 0; k < 64; k++) s += rela[r * 64 + k] * Wr[k * 5 + j];
        g_crel[r * 8 + j] = s;
    }
    for (int i = gtid; i < batch * 5; i += stride) {
        int b = i / 5, j = i % 5;
        int qr = q_rel[b];
        float s = Wqr_b[j];
        #pragma unroll 8
        for (int k = 0; k < 64; k++) s += rela[qr * 64 + k] * Wqr_w[k * 5 + j];
        g_cq[b * 8 + j] = s;
    }
}

// ---------------------------------------------------------------------------
// K1: init — t := 0, wsum := 0, hist := 0, scalars (out needs no zeroing:
//     the final GEMM writes every row with plain stores)
// ---------------------------------------------------------------------------
__global__ void k_init(int n_node)
{
    size_t i      = (size_t)blockIdx.x * blockDim.x + threadIdx.x;
    size_t stride = (size_t)gridDim.x * blockDim.x;

    float4* tp = reinterpret_cast<float4*>(g_t);
    size_t  nt = (size_t)n_node * 16;            // n_node*64/4
    float4  zv = make_float4(0.f, 0.f, 0.f, 0.f);
    for (size_t t = i; t < nt; t += stride) tp[t] = zv;

    for (size_t t = i; t < (size_t)n_node; t += stride) {
        g_hist[t] = 0;
        g_wsum[t] = 0.f;
    }
    if (i == 0) { g_max_enc = 0u; g_sum = 0.f; }
}

// ---------------------------------------------------------------------------
// K2a: histogram over obj
// ---------------------------------------------------------------------------
__global__ void __launch_bounds__(256)
k_hist(const int* __restrict__ edges, int n_edge)
{
    int e = blockIdx.x * 256 + threadIdx.x;
    if (e < n_edge) atomicAdd(&g_hist[edges[(size_t)e * 6 + 5]], 1);
}

// ---------------------------------------------------------------------------
// K2b/c/d: exclusive scan of g_hist -> g_off (+cursor copy)
// ---------------------------------------------------------------------------
__global__ void __launch_bounds__(SCAN_TPB)
k_scan_block(int n)
{
    __shared__ int wsum[8];
    const int tid  = threadIdx.x;
    const int base = blockIdx.x * SCAN_CHUNK + tid * SCAN_EPT;

    int v[SCAN_EPT];
    int s = 0;
    #pragma unroll
    for (int i = 0; i < SCAN_EPT; i++) {
        int idx = base + i;
        v[i] = (idx < n) ? g_hist[idx] : 0;
        s += v[i];
    }
    const int lane = tid & 31, wid = tid >> 5;
    int inc = s;
    #pragma unroll
    for (int off_ = 1; off_ < 32; off_ <<= 1) {
        int t = __shfl_up_sync(0xFFFFFFFFu, inc, off_);
        if (lane >= off_) inc += t;
    }
    if (lane == 31) wsum[wid] = inc;
    __syncthreads();
    if (wid == 0) {
        int ws = (lane < 8) ? wsum[lane] : 0;
        #pragma unroll
        for (int off_ = 1; off_ < 8; off_ <<= 1) {
            int t = __shfl_up_sync(0xFFFFFFFFu, ws, off_);
            if (lane >= off_) ws += t;
        }
        if (lane < 8) wsum[lane] = ws;
    }
    __syncthreads();
    int run = inc - s + (wid > 0 ? wsum[wid - 1] : 0);
    #pragma unroll
    for (int i = 0; i < SCAN_EPT; i++) {
        int idx = base + i;
        if (idx < n) g_off[idx] = run;
        run += v[i];
    }
    if (tid == SCAN_TPB - 1) g_bsum[blockIdx.x] = run;
}

__global__ void k_scan_top(int nb)
{
    __shared__ int sh[NB_MAX];
    int t = threadIdx.x;
    int v = (t < nb) ? g_bsum[t] : 0;
    sh[t] = v;
    __syncthreads();
    #pragma unroll
    for (int off = 1; off < NB_MAX; off <<= 1) {
        int a = (t >= off) ? sh[t - off] : 0;
        __syncthreads();
        sh[t] += a;
        __syncthreads();
    }
    if (t < nb) g_bsum[t] = sh[t] - v;
}

__global__ void k_scan_add(int n, int n_edge)
{
    int i = blockIdx.x * 256 + threadIdx.x;
    if (i < n) {
        int o = g_off[i] + g_bsum[i >> 12];
        g_off[i]    = o;
        g_cursor[i] = o;
    }
    if (i == n) g_off[n] = n_edge;
}

// ---------------------------------------------------------------------------
// K3a: H5 = hidden @ Ws per node (warp per node) — runs BEFORE the scatter
// ---------------------------------------------------------------------------
__global__ void __launch_bounds__(256)
k_h5(const float* __restrict__ hidden,
     const float* __restrict__ Ws,
     int n_node)
{
    const int lane = threadIdx.x & 31;

    float wsa[5], wsb[5];
    #pragma unroll
    for (int j = 0; j < 5; j++) {
        wsa[j] = __ldg(Ws + (2 * lane) * 5 + j);
        wsb[j] = __ldg(Ws + (2 * lane + 1) * 5 + j);
    }

    const int warps_total = gridDim.x * (blockDim.x >> 5);
    int w = blockIdx.x * (blockDim.x >> 5) + (threadIdx.x >> 5);

    for (int node = w; node < n_node; node += warps_total) {
        const float2 h = *reinterpret_cast<const float2*>(hidden + (size_t)node * 64 + 2 * lane);
        float p0 = h.x * wsa[0] + h.y * wsb[0];
        float p1 = h.x * wsa[1] + h.y * wsb[1];
        float p2 = h.x * wsa[2] + h.y * wsb[2];
        float p3 = h.x * wsa[3] + h.y * wsb[3];
        float p4 = h.x * wsa[4] + h.y * wsb[4];
        #pragma unroll
        for (int off = 16; off > 0; off >>= 1) {
            p0 += __shfl_xor_sync(0xFFFFFFFFu, p0, off);
            p1 += __shfl_xor_sync(0xFFFFFFFFu, p1, off);
            p2 += __shfl_xor_sync(0xFFFFFFFFu, p2, off);
            p3 += __shfl_xor_sync(0xFFFFFFFFu, p3, off);
            p4 += __shfl_xor_sync(0xFFFFFFFFu, p4, off);
        }
        if (lane == 0) {
            float* dst = g_h5 + (size_t)node * 8;
            *reinterpret_cast<float4*>(dst) = make_float4(p0, p1, p2, p3);
            dst[4] = p4;
        }
    }
}

// ---------------------------------------------------------------------------
// K2e: scatter edges into obj-grouped arrays + alpha computed inline
// ---------------------------------------------------------------------------
__global__ void __launch_bounds__(256)
k_scatter(const int* __restrict__ edges,
          const float* __restrict__ wa, const float* __restrict__ wab,
          int n_edge)
{
    int e = blockIdx.x * 256 + threadIdx.x;
    if (e >= n_edge) return;
    const int* ep = edges + (size_t)e * 6;
    int r_idx = ep[0];
    int rel   = ep[2];
    int sub   = ep[4];
    int obj   = ep[5];

    int pos = atomicAdd(&g_cursor[obj], 1);
    g_esub[pos] = sub;
    g_erel[pos] = rel;
    g_eobj[pos] = obj;

    const float4 h4 = *reinterpret_cast<const float4*>(g_h5 + (size_t)sub * 8);
    const float  h5 = g_h5[(size_t)sub * 8 + 4];
    const float4 c4 = *reinterpret_cast<const float4*>(g_crel + rel * 8);
    const float  c5 = g_crel[rel * 8 + 4];
    const float4 q4 = *reinterpret_cast<const float4*>(g_cq + r_idx * 8);
    const float  q5 = g_cq[r_idx * 8 + 4];

    float z = __ldg(wab);
    z += fmaxf(h4.x + c4.x + q4.x, 0.f) * __ldg(wa + 0);
    z += fmaxf(h4.y + c4.y + q4.y, 0.f) * __ldg(wa + 1);
    z += fmaxf(h4.z + c4.z + q4.z, 0.f) * __ldg(wa + 2);
    z += fmaxf(h4.w + c4.w + q4.w, 0.f) * __ldg(wa + 3);
    z += fmaxf(h5   + c5   + q5,   0.f) * __ldg(wa + 4);
    g_alpha[pos] = 1.f / (1.f + expf(-z));
}

// ---------------------------------------------------------------------------
// K3c: segment max — warp per node, serial edge walk.
//      Epilogue: s0 = agg.v0, s1 = agg.v1 computed from registers (the old
//      GEMM-on-agg s0/s1 pass, folded here for zero extra traffic).
// ---------------------------------------------------------------------------
__global__ void __launch_bounds__(256)
k_edge2(const float* __restrict__ hidden,
        const float* __restrict__ rela,
        int n_node)
{
    const int lane = threadIdx.x & 31;

    // v0/v1 slices for this lane's two dims
    const float v0a = g_Mext[(2 * lane)     * 66 + 64];
    const float v1a = g_Mext[(2 * lane)     * 66 + 65];
    const float v0b = g_Mext[(2 * lane + 1) * 66 + 64];
    const float v1b = g_Mext[(2 * lane + 1) * 66 + 65];

    const int warps_total = gridDim.x * (blockDim.x >> 5);
    int w = blockIdx.x * (blockDim.x >> 5) + (threadIdx.x >> 5);

    for (int node = w; node < n_node; node += warps_total) {
        const int start = g_off[node];
        const int end   = g_off[node + 1];

        float m0 = -FLT_MAX, m1 = -FLT_MAX;
        for (int i = start; i < end; i++) {
            const float alpha = __ldg(g_alpha + i);
            const int   sub   = g_esub[i];
            const int   rel   = g_erel[i];
            const float2 hs = *reinterpret_cast<const float2*>(hidden + (size_t)sub * 64 + 2 * lane);
            const float2 hr = *reinterpret_cast<const float2*>(rela   + (size_t)rel * 64 + 2 * lane);
            m0 = fmaxf(m0, alpha * (hs.x - hr.x));
            m1 = fmaxf(m1, alpha * (hs.y - hr.y));
        }
        float2 o = (end > start) ? make_float2(m0, m1) : make_float2(0.f, 0.f);
        *reinterpret_cast<float2*>(g_agg + (size_t)node * 64 + 2 * lane) = o;

        // s0/s1 epilogue (warp reduce)
        float s0p = o.x * v0a + o.y * v0b;
        float s1p = o.x * v1a + o.y * v1b;
        #pragma unroll
        for (int off = 16; off > 0; off >>= 1) {
            s0p += __shfl_xor_sync(0xFFFFFFFFu, s0p, off);
            s1p += __shfl_xor_sync(0xFFFFFFFFu, s1p, off);
        }
        if (lane == 0) {
            g_s0[node] = s0p;
            g_s1[node] = s1p;
        }
    }
}

// ---------------------------------------------------------------------------
// K5: edge scores + global max
// ---------------------------------------------------------------------------
__global__ void __launch_bounds__(256)
k_score(const float* __restrict__ attn_b, int n_edge)
{
    const int e = blockIdx.x * 256 + threadIdx.x;
    float sc = -FLT_MAX;
    if (e < n_edge) {
        float s = g_s0[g_esub[e]] + g_s1[g_eobj[e]] + __ldg(attn_b);
        sc = (s > 0.f) ? s : 0.2f * s;
        g_scores[e] = sc;
    }
    __shared__ float red[8];
    const int lane = threadIdx.x & 31, wid = threadIdx.x >> 5;
    #pragma unroll
    for (int off = 16; off > 0; off >>= 1)
        sc = fmaxf(sc, __shfl_xor_sync(0xFFFFFFFFu, sc, off));
    if (lane == 0) red[wid] = sc;
    __syncthreads();
    if (wid == 0) {
        float v = (lane < 8) ? red[lane] : -FLT_MAX;
        #pragma unroll
        for (int off = 4; off > 0; off >>= 1)
            v = fmaxf(v, __shfl_xor_sync(0xFFFFFFFFu, v, off));
        if (lane == 0) atomicMax(&g_max_enc, encf(v));
    }
}

// ---------------------------------------------------------------------------
// K6: exp(score - max) in place + global sum
// ---------------------------------------------------------------------------
__global__ void __launch_bounds__(256)
k_expsum(int n_edge)
{
    const float gm = decf(g_max_enc);
    const int e = blockIdx.x * 256 + threadIdx.x;
    float v = 0.f;
    if (e < n_edge) {
        v = expf(g_scores[e] - gm);
        g_scores[e] = v;
    }
    __shared__ float red[8];
    const int lane = threadIdx.x & 31, wid = threadIdx.x >> 5;
    #pragma unroll
    for (int off = 16; off > 0; off >>= 1)
        v += __shfl_xor_sync(0xFFFFFFFFu, v, off);
    if (lane == 0) red[wid] = v;
    __syncthreads();
    if (wid == 0) {
        float s = (lane < 8) ? red[lane] : 0.f;
        #pragma unroll
        for (int off = 4; off > 0; off >>= 1)
            s += __shfl_xor_sync(0xFFFFFFFFu, s, off);
        if (lane == 0) atomicAdd(&g_sum, s);
    }
}

// ---------------------------------------------------------------------------
// K7: t-accumulation — t[sub] += w_e * agg[obj]; wsum[sub] += w_e
//     16 threads per edge, vectorized red.global.add.v4.f32
// ---------------------------------------------------------------------------
__global__ void __launch_bounds__(256)
k_taccum(int n_edge)
{
    const float inv = 1.f / g_sum;
    const int t = blockIdx.x * 256 + threadIdx.x;
    const int e = t >> 4;
    const int q = t & 15;
    if (e >= n_edge) return;

    const int sub = g_esub[e];
    const int obj = g_eobj[e];
    const float wgt = g_scores[e] * inv;
    const float4 m = *reinterpret_cast<const float4*>(
        g_agg + (size_t)obj * 64 + q * 4);
    float* op = g_t + (size_t)sub * 64 + q * 4;
    asm volatile("red.global.add.v4.f32 [%0], {%1, %2, %3, %4};"
                 :: "l"(op), "f"(wgt * m.x), "f"(wgt * m.y),
                    "f"(wgt * m.z), "f"(wgt * m.w)
                 : "memory");
    if (q == 0)
        asm volatile("red.global.add.f32 [%0], %1;"
                     :: "l"(g_wsum + sub), "f"(wgt) : "memory");
}

// ---------------------------------------------------------------------------
// K8: final GEMM — out = t@M + wsum*b; plain coalesced stores, all rows.
//     256 rows x 64 cols per block, 256 threads, 8x8 f32x2 thread tile.
// ---------------------------------------------------------------------------
#define AS_STRIDE 68
#define GEMM_ROWS 256
#define GEMM_SMEM ((GEMM_ROWS * AS_STRIDE + 64 * 64) * 4)

__global__ void __launch_bounds__(256, 2)
k_gemm(int n_node, const float* __restrict__ Wnode_b, float* __restrict__ out)
{
    extern __shared__ float smem[];
    float* As  = smem;                            // 256 * 68
    float* MsL = smem + GEMM_ROWS * AS_STRIDE;    // 64 * 64, [k][half][tx][4]

    const int tid = threadIdx.x;
    for (int i = tid; i < 64 * 64; i += 256) {
        int k = i >> 6, c = i & 63;
        MsL[k * 64 + ((c & 4) ? 32 : 0) + (c >> 3) * 4 + (c & 3)] =
            g_Mext[k * 66 + c];
    }

    const int rb = blockIdx.x * GEMM_ROWS;
    const float4* src = reinterpret_cast<const float4*>(g_t + (size_t)rb * 64);
    const bool full = (rb + GEMM_ROWS <= n_node);

    #pragma unroll
    for (int t = 0; t < 16; t++) {
        int vidx = tid + t * 256;
        int r  = vidx >> 4;
        int k4 = (vidx & 15) * 4;
        float4 u = make_float4(0.f, 0.f, 0.f, 0.f);
        if (full || rb + r < n_node) u = src[vidx];
        *reinterpret_cast<float4*>(As + r * AS_STRIDE + k4) = u;
    }
    __syncthreads();

    const int tx = tid & 7;
    const int ty = tid >> 3;

    unsigned long long acc[8][4];
    #pragma unroll
    for (int i = 0; i < 8; i++)
        #pragma unroll
        for (int c = 0; c < 4; c++) acc[i][c] = 0ull;

    const float* arow  = As + ty * 8 * AS_STRIDE;
    const float* mbase = MsL + tx * 4;

    for (int k4 = 0; k4 < 64; k4 += 4) {
        float4 a[8];
        #pragma unroll
        for (int i = 0; i < 8; i++)
            a[i] = *reinterpret_cast<const float4*>(arow + i * AS_STRIDE + k4);

        #pragma unroll
        for (int kk = 0; kk < 4; kk++) {
            const ulonglong2 mp0 = *reinterpret_cast<const ulonglong2*>(mbase + (k4 + kk) * 64);
            const ulonglong2 mp1 = *reinterpret_cast<const ulonglong2*>(mbase + (k4 + kk) * 64 + 32);
            #pragma unroll
            for (int i = 0; i < 8; i++) {
                const float av = (kk == 0) ? a[i].x : (kk == 1) ? a[i].y
                               : (kk == 2) ? a[i].z : a[i].w;
                const unsigned long long aa = pack2(av);
                ffma2(acc[i][0], aa, mp0.x);
                ffma2(acc[i][1], aa, mp0.y);
                ffma2(acc[i][2], aa, mp1.x);
                ffma2(acc[i][3], aa, mp1.y);
            }
        }
    }

    const float4 b0 = *reinterpret_cast<const float4*>(Wnode_b + tx * 8);
    const float4 b1 = *reinterpret_cast<const float4*>(Wnode_b + tx * 8 + 4);
    #pragma unroll
    for (int i = 0; i < 8; i++) {
        int grow = rb + ty * 8 + i;
        if (grow < n_node) {
            const float ws = g_wsum[grow];
            float2 a0 = unpack2(acc[i][0]);
            float2 a1 = unpack2(acc[i][1]);
            float2 a2 = unpack2(acc[i][2]);
            float2 a3 = unpack2(acc[i][3]);
            float* op = out + (size_t)grow * 64 + tx * 8;
            *reinterpret_cast<float4*>(op) =
                make_float4(a0.x + ws * b0.x, a0.y + ws * b0.y,
                            a1.x + ws * b0.z, a1.y + ws * b0.w);
            *reinterpret_cast<float4*>(op + 4) =
                make_float4(a2.x + ws * b1.x, a2.y + ws * b1.y,
                            a3.x + ws * b1.z, a3.y + ws * b1.w);
        }
    }
}

// ---------------------------------------------------------------------------
// kernel_launch
// ---------------------------------------------------------------------------
extern "C" void kernel_launch(void* const* d_in, const int* in_sizes, int n_in,
                              void* d_out, int out_size)
{
    const float* hidden    = (const float*)d_in[0];
    const float* rela      = (const float*)d_in[1];
    const float* Ws        = (const float*)d_in[2];
    const float* Wr        = (const float*)d_in[3];
    const float* Wqr_w     = (const float*)d_in[4];
    const float* Wqr_b     = (const float*)d_in[5];
    const float* walpha_w  = (const float*)d_in[6];
    const float* walpha_b  = (const float*)d_in[7];
    const float* Wh        = (const float*)d_in[8];
    const float* attn_fc_w = (const float*)d_in[9];
    const float* attn_fc_b = (const float*)d_in[10];
    const float* Wnode_w   = (const float*)d_in[11];
    const float* Wnode_b   = (const float*)d_in[12];
    const int*   q_rel     = (const int*)d_in[14];
    const int*   edges     = (const int*)d_in[15];
    float*       out       = (float*)d_out;

    const int n_edge = in_sizes[15] / 6;
    const int n_node = in_sizes[16] / 2;
    const int nrel   = in_sizes[1] / 64;
    const int batch  = in_sizes[14];
    const int nb     = (n_node + SCAN_CHUNK - 1) / SCAN_CHUNK;

    static bool attr_set = false;
    if (!attr_set) {
        cudaFuncSetAttribute(k_gemm, cudaFuncAttributeMaxDynamicSharedMemorySize,
                             GEMM_SMEM);
        attr_set = true;
    }

    // small tables
    k_setup<<<32, 256>>>(Wh, Wnode_w, attn_fc_w, rela, Wr, Wqr_w, Wqr_b,
                         q_rel, nrel, batch);

    // init t + wsum + hist + scalars
    k_init<<<4096, 256>>>(n_node);

    // H5 precompute (must precede k_scatter)
    k_h5<<<2368, 256>>>(hidden, Ws, n_node);

    // counting sort of edges by obj (+alpha inside the scatter)
    k_hist<<<(n_edge + 255) / 256, 256>>>(edges, n_edge);
    k_scan_block<<<nb, SCAN_TPB>>>(n_node);
    k_scan_top<<<1, NB_MAX>>>(nb);
    k_scan_add<<<(n_node + 256) / 256, 256>>>(n_node, n_edge);
    k_scatter<<<(n_edge + 255) / 256, 256>>>(edges, walpha_w, walpha_b, n_edge);

    // segment max + s0/s1 epilogue (warp per node)
    k_edge2<<<2368, 256>>>(hidden, rela, n_node);

    // softmax statistics
    k_score<<<(n_edge + 255) / 256, 256>>>(attn_fc_b, n_edge);
    k_expsum<<<(n_edge + 255) / 256, 256>>>(n_edge);

    // t/wsum accumulation (16 threads/edge, RED.128)
    k_taccum<<<(n_edge * 16 + 255) / 256, 256>>>(n_edge);

    // final GEMM: out = t@M + wsum*b (plain stores)
    k_gemm<<<(n_node + GEMM_ROWS - 1) / GEMM_ROWS, 256, GEMM_SMEM>>>(
        n_node, Wnode_b, out);
}

// round 14
// speedup vs baseline: 1.1244x; 1.0017x over previous
#include <cuda_runtime.h>
#include <cfloat>
#include <cstdint>

// ---------------------------------------------------------------------------
// Problem-size constants
// ---------------------------------------------------------------------------
#define N_NODE_MAX 500000
#define N_EDGE_MAX 1000000
#define NREL_MAX   512
#define BATCH_MAX  64

#define SCAN_TPB   256
#define SCAN_EPT   16
#define SCAN_CHUNK 4096
#define NB_MAX     128

// ---------------------------------------------------------------------------
// Device scratch
// ---------------------------------------------------------------------------
__device__ float    g_agg[(size_t)N_NODE_MAX * 64];      // segment-max result
__device__ float    g_t[(size_t)N_NODE_MAX * 64];        // sum_e w_e * agg[obj_e]
__device__ float    g_wsum[N_NODE_MAX];                  // sum_e w_e (per sub)
__device__ float    g_h5[(size_t)N_NODE_MAX * 8];        // hidden@Ws (padded)
__device__ float    g_s0[N_NODE_MAX];
__device__ float    g_s1[N_NODE_MAX];
__device__ float    g_scores[N_EDGE_MAX];
__device__ float    g_Mext[64 * 66];                     // [k][c]: c<64 M, 64 v0, 65 v1
__device__ float    g_crel[NREL_MAX * 8];
__device__ float    g_cq[BATCH_MAX * 8];
__device__ unsigned g_max_enc;
__device__ float    g_sum;

// edge staging (original order) + sorted packed records
__device__ int4     g_estage[N_EDGE_MAX];   // (r_idx, rel, sub, obj)
__device__ int4     g_epack[N_EDGE_MAX];    // (sub, rel, obj, alpha_bits), obj-sorted

// counting-sort scratch (by obj)
__device__ int      g_hist[N_NODE_MAX];
__device__ int      g_off[N_NODE_MAX + 1];
__device__ int      g_cursor[N_NODE_MAX];
__device__ int      g_bsum[NB_MAX];

// ---------------------------------------------------------------------------
// Order-preserving float <-> uint encoding
// ---------------------------------------------------------------------------
__device__ __forceinline__ unsigned encf(float x) {
    unsigned u = __float_as_uint(x);
    return (u & 0x80000000u) ? ~u : (u | 0x80000000u);
}
__device__ __forceinline__ float decf(unsigned u) {
    return (u & 0x80000000u) ? __uint_as_float(u & 0x7FFFFFFFu)
                             : __uint_as_float(~u);
}

// ---------------------------------------------------------------------------
// Packed f32x2 helpers
// ---------------------------------------------------------------------------
__device__ __forceinline__ unsigned long long pack2(float a) {
    unsigned long long r;
    asm("mov.b64 %0, {%1, %1};" : "=l"(r) : "r"(__float_as_uint(a)));
    return r;
}
__device__ __forceinline__ void ffma2(unsigned long long& d,
                                      unsigned long long a,
                                      unsigned long long b) {
    asm("fma.rn.f32x2 %0, %1, %2, %0;" : "+l"(d) : "l"(a), "l"(b));
}
__device__ __forceinline__ float2 unpack2(unsigned long long v) {
    unsigned lo, hi;
    asm("mov.b64 {%0, %1}, %2;" : "=r"(lo), "=r"(hi) : "l"(v));
    return make_float2(__uint_as_float(lo), __uint_as_float(hi));
}

// ---------------------------------------------------------------------------
// K0: setup — M_ext = [Wh@Wnode | Wh@w0 | Wh@w1], crel, cq
// ---------------------------------------------------------------------------
__global__ void k_setup(const float* __restrict__ Wh,
                        const float* __restrict__ Wnode,
                        const float* __restrict__ attn_w,
                        const float* __restrict__ rela,
                        const float* __restrict__ Wr,
                        const float* __restrict__ Wqr_w,
                        const float* __restrict__ Wqr_b,
                        const int*   __restrict__ q_rel,
                        int nrel, int batch)
{
    int gtid   = blockIdx.x * blockDim.x + threadIdx.x;
    int stride = gridDim.x * blockDim.x;

    for (int i = gtid; i < 64 * 66; i += stride) {
        int k = i / 66, c = i % 66;
        float s = 0.f;
        if (c < 64) {
            #pragma unroll 8
            for (int j = 0; j < 64; j++) s += Wh[k * 64 + j] * Wnode[j * 64 + c];
        } else {
            const float* w = attn_w + (c - 64) * 64;
            #pragma unroll 8
            for (int j = 0; j < 64; j++) s += Wh[k * 64 + j] * w[j];
        }
        g_Mext[i] = s;
    }
    for (int i = gtid; i < nrel * 5; i += stride) {
        int r = i / 5, j = i % 5;
        float s = 0.f;
        #pragma unroll 8
        for (int k = 0; k < 64; k++) s += rela[r * 64 + k] * Wr[k * 5 + j];
        g_crel[r * 8 + j] = s;
    }
    for (int i = gtid; i < batch * 5; i += stride) {
        int b = i / 5, j = i % 5;
        int qr = q_rel[b];
        float s = Wqr_b[j];
        #pragma unroll 8
        for (int k = 0; k < 64; k++) s += rela[qr * 64 + k] * Wqr_w[k * 5 + j];
        g_cq[b * 8 + j] = s;
    }
}

// ---------------------------------------------------------------------------
// K1: init — t := 0, wsum := 0, hist := 0, scalars
// ---------------------------------------------------------------------------
__global__ void k_init(int n_node)
{
    size_t i      = (size_t)blockIdx.x * blockDim.x + threadIdx.x;
    size_t stride = (size_t)gridDim.x * blockDim.x;

    float4* tp = reinterpret_cast<float4*>(g_t);
    size_t  nt = (size_t)n_node * 16;
    float4  zv = make_float4(0.f, 0.f, 0.f, 0.f);
    for (size_t t = i; t < nt; t += stride) tp[t] = zv;

    for (size_t t = i; t < (size_t)n_node; t += stride) {
        g_hist[t] = 0;
        g_wsum[t] = 0.f;
    }
    if (i == 0) { g_max_enc = 0u; g_sum = 0.f; }
}

// ---------------------------------------------------------------------------
// K2a: histogram over obj + stage compact edge tuples (coalesced 16B)
// ---------------------------------------------------------------------------
__global__ void __launch_bounds__(256)
k_hist(const int* __restrict__ edges, int n_edge)
{
    int e = blockIdx.x * 256 + threadIdx.x;
    if (e >= n_edge) return;
    const int* ep = edges + (size_t)e * 6;
    int2 i01 = *reinterpret_cast<const int2*>(ep);       // r_idx
    int2 i23 = *reinterpret_cast<const int2*>(ep + 2);   // rel
    int2 i45 = *reinterpret_cast<const int2*>(ep + 4);   // sub, obj
    g_estage[e] = make_int4(i01.x, i23.x, i45.x, i45.y);
    atomicAdd(&g_hist[i45.y], 1);
}

// ---------------------------------------------------------------------------
// K2b/c/d: exclusive scan of g_hist -> g_off (+cursor copy)
// ---------------------------------------------------------------------------
__global__ void __launch_bounds__(SCAN_TPB)
k_scan_block(int n)
{
    __shared__ int wsum[8];
    const int tid  = threadIdx.x;
    const int base = blockIdx.x * SCAN_CHUNK + tid * SCAN_EPT;

    int v[SCAN_EPT];
    int s = 0;
    #pragma unroll
    for (int i = 0; i < SCAN_EPT; i++) {
        int idx = base + i;
        v[i] = (idx < n) ? g_hist[idx] : 0;
        s += v[i];
    }
    const int lane = tid & 31, wid = tid >> 5;
    int inc = s;
    #pragma unroll
    for (int off_ = 1; off_ < 32; off_ <<= 1) {
        int t = __shfl_up_sync(0xFFFFFFFFu, inc, off_);
        if (lane >= off_) inc += t;
    }
    if (lane == 31) wsum[wid] = inc;
    __syncthreads();
    if (wid == 0) {
        int ws = (lane < 8) ? wsum[lane] : 0;
        #pragma unroll
        for (int off_ = 1; off_ < 8; off_ <<= 1) {
            int t = __shfl_up_sync(0xFFFFFFFFu, ws, off_);
            if (lane >= off_) ws += t;
        }
        if (lane < 8) wsum[lane] = ws;
    }
    __syncthreads();
    int run = inc - s + (wid > 0 ? wsum[wid - 1] : 0);
    #pragma unroll
    for (int i = 0; i < SCAN_EPT; i++) {
        int idx = base + i;
        if (idx < n) g_off[idx] = run;
        run += v[i];
    }
    if (tid == SCAN_TPB - 1) g_bsum[blockIdx.x] = run;
}

__global__ void k_scan_top(int nb)
{
    __shared__ int sh[NB_MAX];
    int t = threadIdx.x;
    int v = (t < nb) ? g_bsum[t] : 0;
    sh[t] = v;
    __syncthreads();
    #pragma unroll
    for (int off = 1; off < NB_MAX; off <<= 1) {
        int a = (t >= off) ? sh[t - off] : 0;
        __syncthreads();
        sh[t] += a;
        __syncthreads();
    }
    if (t < nb) g_bsum[t] = sh[t] - v;
}

__global__ void k_scan_add(int n, int n_edge)
{
    int i = blockIdx.x * 256 + threadIdx.x;
    if (i < n) {
        int o = g_off[i] + g_bsum[i >> 12];
        g_off[i]    = o;
        g_cursor[i] = o;
    }
    if (i == n) g_off[n] = n_edge;
}

// ---------------------------------------------------------------------------
// K3a: H5 = hidden @ Ws per node (warp per node) — runs BEFORE the scatter
// ---------------------------------------------------------------------------
__global__ void __launch_bounds__(256)
k_h5(const float* __restrict__ hidden,
     const float* __restrict__ Ws,
     int n_node)
{
    const int lane = threadIdx.x & 31;

    float wsa[5], wsb[5];
    #pragma unroll
    for (int j = 0; j < 5; j++) {
        wsa[j] = __ldg(Ws + (2 * lane) * 5 + j);
        wsb[j] = __ldg(Ws + (2 * lane + 1) * 5 + j);
    }

    const int warps_total = gridDim.x * (blockDim.x >> 5);
    int w = blockIdx.x * (blockDim.x >> 5) + (threadIdx.x >> 5);

    for (int node = w; node < n_node; node += warps_total) {
        const float2 h = *reinterpret_cast<const float2*>(hidden + (size_t)node * 64 + 2 * lane);
        float p0 = h.x * wsa[0] + h.y * wsb[0];
        float p1 = h.x * wsa[1] + h.y * wsb[1];
        float p2 = h.x * wsa[2] + h.y * wsb[2];
        float p3 = h.x * wsa[3] + h.y * wsb[3];
        float p4 = h.x * wsa[4] + h.y * wsb[4];
        #pragma unroll
        for (int off = 16; off > 0; off >>= 1) {
            p0 += __shfl_xor_sync(0xFFFFFFFFu, p0, off);
            p1 += __shfl_xor_sync(0xFFFFFFFFu, p1, off);
            p2 += __shfl_xor_sync(0xFFFFFFFFu, p2, off);
            p3 += __shfl_xor_sync(0xFFFFFFFFu, p3, off);
            p4 += __shfl_xor_sync(0xFFFFFFFFu, p4, off);
        }
        if (lane == 0) {
            float* dst = g_h5 + (size_t)node * 8;
            *reinterpret_cast<float4*>(dst) = make_float4(p0, p1, p2, p3);
            dst[4] = p4;
        }
    }
}

// ---------------------------------------------------------------------------
// K2e: scatter staged edges into obj-grouped packed records + inline alpha
// ---------------------------------------------------------------------------
__global__ void __launch_bounds__(256)
k_scatter(const float* __restrict__ wa, const float* __restrict__ wab,
          int n_edge)
{
    int e = blockIdx.x * 256 + threadIdx.x;
    if (e >= n_edge) return;
    const int4 st = g_estage[e];        // (r_idx, rel, sub, obj)
    const int r_idx = st.x, rel = st.y, sub = st.z, obj = st.w;

    int pos = atomicAdd(&g_cursor[obj], 1);

    const float4 h4 = *reinterpret_cast<const float4*>(g_h5 + (size_t)sub * 8);
    const float  h5 = g_h5[(size_t)sub * 8 + 4];
    const float4 c4 = *reinterpret_cast<const float4*>(g_crel + rel * 8);
    const float  c5 = g_crel[rel * 8 + 4];
    const float4 q4 = *reinterpret_cast<const float4*>(g_cq + r_idx * 8);
    const float  q5 = g_cq[r_idx * 8 + 4];

    float z = __ldg(wab);
    z += fmaxf(h4.x + c4.x + q4.x, 0.f) * __ldg(wa + 0);
    z += fmaxf(h4.y + c4.y + q4.y, 0.f) * __ldg(wa + 1);
    z += fmaxf(h4.z + c4.z + q4.z, 0.f) * __ldg(wa + 2);
    z += fmaxf(h4.w + c4.w + q4.w, 0.f) * __ldg(wa + 3);
    z += fmaxf(h5   + c5   + q5,   0.f) * __ldg(wa + 4);
    const float alpha = 1.f / (1.f + expf(-z));

    g_epack[pos] = make_int4(sub, rel, obj, __float_as_int(alpha));
}

// ---------------------------------------------------------------------------
// K3c: segment max — warp per node, serial edge walk (one LDG.128 per edge
//      for the packed record). Epilogue: s0/s1 from registers.
// ---------------------------------------------------------------------------
__global__ void __launch_bounds__(256)
k_edge2(const float* __restrict__ hidden,
        const float* __restrict__ rela,
        int n_node)
{
    const int lane = threadIdx.x & 31;

    const float v0a = g_Mext[(2 * lane)     * 66 + 64];
    const float v1a = g_Mext[(2 * lane)     * 66 + 65];
    const float v0b = g_Mext[(2 * lane + 1) * 66 + 64];
    const float v1b = g_Mext[(2 * lane + 1) * 66 + 65];

    const int warps_total = gridDim.x * (blockDim.x >> 5);
    int w = blockIdx.x * (blockDim.x >> 5) + (threadIdx.x >> 5);

    for (int node = w; node < n_node; node += warps_total) {
        const int start = g_off[node];
        const int end   = g_off[node + 1];

        float m0 = -FLT_MAX, m1 = -FLT_MAX;
        for (int i = start; i < end; i++) {
            const int4 p = g_epack[i];                 // broadcast LDG.128
            const int   sub   = p.x;
            const int   rel   = p.y;
            const float alpha = __int_as_float(p.w);
            const float2 hs = *reinterpret_cast<const float2*>(hidden + (size_t)sub * 64 + 2 * lane);
            const float2 hr = *reinterpret_cast<const float2*>(rela   + (size_t)rel * 64 + 2 * lane);
            m0 = fmaxf(m0, alpha * (hs.x - hr.x));
            m1 = fmaxf(m1, alpha * (hs.y - hr.y));
        }
        float2 o = (end > start) ? make_float2(m0, m1) : make_float2(0.f, 0.f);
        *reinterpret_cast<float2*>(g_agg + (size_t)node * 64 + 2 * lane) = o;

        float s0p = o.x * v0a + o.y * v0b;
        float s1p = o.x * v1a + o.y * v1b;
        #pragma unroll
        for (int off = 16; off > 0; off >>= 1) {
            s0p += __shfl_xor_sync(0xFFFFFFFFu, s0p, off);
            s1p += __shfl_xor_sync(0xFFFFFFFFu, s1p, off);
        }
        if (lane == 0) {
            g_s0[node] = s0p;
            g_s1[node] = s1p;
        }
    }
}

// ---------------------------------------------------------------------------
// K5: edge scores + global max (raw scores stored; exp NOT materialized)
// ---------------------------------------------------------------------------
__global__ void __launch_bounds__(256)
k_score(const float* __restrict__ attn_b, int n_edge)
{
    const int e = blockIdx.x * 256 + threadIdx.x;
    float sc = -FLT_MAX;
    if (e < n_edge) {
        const int4 p = g_epack[e];
        float s = g_s0[p.x] + g_s1[p.z] + __ldg(attn_b);
        sc = (s > 0.f) ? s : 0.2f * s;
        g_scores[e] = sc;
    }
    __shared__ float red[8];
    const int lane = threadIdx.x & 31, wid = threadIdx.x >> 5;
    #pragma unroll
    for (int off = 16; off > 0; off >>= 1)
        sc = fmaxf(sc, __shfl_xor_sync(0xFFFFFFFFu, sc, off));
    if (lane == 0) red[wid] = sc;
    __syncthreads();
    if (wid == 0) {
        float v = (lane < 8) ? red[lane] : -FLT_MAX;
        #pragma unroll
        for (int off = 4; off > 0; off >>= 1)
            v = fmaxf(v, __shfl_xor_sync(0xFFFFFFFFu, v, off));
        if (lane == 0) atomicMax(&g_max_enc, encf(v));
    }
}

// ---------------------------------------------------------------------------
// K6: global sum of exp(score - max) — reduce only, no store
// ---------------------------------------------------------------------------
__global__ void __launch_bounds__(256)
k_sum(int n_edge)
{
    const float gm = decf(g_max_enc);
    const int e = blockIdx.x * 256 + threadIdx.x;
    float v = 0.f;
    if (e < n_edge) v = expf(g_scores[e] - gm);
    __shared__ float red[8];
    const int lane = threadIdx.x & 31, wid = threadIdx.x >> 5;
    #pragma unroll
    for (int off = 16; off > 0; off >>= 1)
        v += __shfl_xor_sync(0xFFFFFFFFu, v, off);
    if (lane == 0) red[wid] = v;
    __syncthreads();
    if (wid == 0) {
        float s = (lane < 8) ? red[lane] : 0.f;
        #pragma unroll
        for (int off = 4; off > 0; off >>= 1)
            s += __shfl_xor_sync(0xFFFFFFFFu, s, off);
        if (lane == 0) atomicAdd(&g_sum, s);
    }
}

// ---------------------------------------------------------------------------
// K7: t-accumulation — t[sub] += w_e * agg[obj]; wsum[sub] += w_e
//     16 threads per edge; w_e = exp(score-gm)/sum recomputed inline.
// ---------------------------------------------------------------------------
__global__ void __launch_bounds__(256)
k_taccum(int n_edge)
{
    const float inv = 1.f / g_sum;
    const float gm  = decf(g_max_enc);
    const int t = blockIdx.x * 256 + threadIdx.x;
    const int e = t >> 4;
    const int q = t & 15;
    if (e >= n_edge) return;

    const int4 p = g_epack[e];          // broadcast across the 16 lanes
    const int sub = p.x;
    const int obj = p.z;
    const float wgt = expf(__ldg(g_scores + e) - gm) * inv;
    const float4 m = *reinterpret_cast<const float4*>(
        g_agg + (size_t)obj * 64 + q * 4);
    float* op = g_t + (size_t)sub * 64 + q * 4;
    asm volatile("red.global.add.v4.f32 [%0], {%1, %2, %3, %4};"
                 :: "l"(op), "f"(wgt * m.x), "f"(wgt * m.y),
                    "f"(wgt * m.z), "f"(wgt * m.w)
                 : "memory");
    if (q == 0)
        asm volatile("red.global.add.f32 [%0], %1;"
                     :: "l"(g_wsum + sub), "f"(wgt) : "memory");
}

// ---------------------------------------------------------------------------
// K8: final GEMM — out = t@M + wsum*b; plain coalesced stores, all rows.
// ---------------------------------------------------------------------------
#define AS_STRIDE 68
#define GEMM_ROWS 256
#define GEMM_SMEM ((GEMM_ROWS * AS_STRIDE + 64 * 64) * 4)

__global__ void __launch_bounds__(256, 2)
k_gemm(int n_node, const float* __restrict__ Wnode_b, float* __restrict__ out)
{
    extern __shared__ float smem[];
    float* As  = smem;                            // 256 * 68
    float* MsL = smem + GEMM_ROWS * AS_STRIDE;    // 64 * 64, [k][half][tx][4]

    const int tid = threadIdx.x;
    for (int i = tid; i < 64 * 64; i += 256) {
        int k = i >> 6, c = i & 63;
        MsL[k * 64 + ((c & 4) ? 32 : 0) + (c >> 3) * 4 + (c & 3)] =
            g_Mext[k * 66 + c];
    }

    const int rb = blockIdx.x * GEMM_ROWS;
    const float4* src = reinterpret_cast<const float4*>(g_t + (size_t)rb * 64);
    const bool full = (rb + GEMM_ROWS <= n_node);

    #pragma unroll
    for (int t = 0; t < 16; t++) {
        int vidx = tid + t * 256;
        int r  = vidx >> 4;
        int k4 = (vidx & 15) * 4;
        float4 u = make_float4(0.f, 0.f, 0.f, 0.f);
        if (full || rb + r < n_node) u = src[vidx];
        *reinterpret_cast<float4*>(As + r * AS_STRIDE + k4) = u;
    }
    __syncthreads();

    const int tx = tid & 7;
    const int ty = tid >> 3;

    unsigned long long acc[8][4];
    #pragma unroll
    for (int i = 0; i < 8; i++)
        #pragma unroll
        for (int c = 0; c < 4; c++) acc[i][c] = 0ull;

    const float* arow  = As + ty * 8 * AS_STRIDE;
    const float* mbase = MsL + tx * 4;

    for (int k4 = 0; k4 < 64; k4 += 4) {
        float4 a[8];
        #pragma unroll
        for (int i = 0; i < 8; i++)
            a[i] = *reinterpret_cast<const float4*>(arow + i * AS_STRIDE + k4);

        #pragma unroll
        for (int kk = 0; kk < 4; kk++) {
            const ulonglong2 mp0 = *reinterpret_cast<const ulonglong2*>(mbase + (k4 + kk) * 64);
            const ulonglong2 mp1 = *reinterpret_cast<const ulonglong2*>(mbase + (k4 + kk) * 64 + 32);
            #pragma unroll
            for (int i = 0; i < 8; i++) {
                const float av = (kk == 0) ? a[i].x : (kk == 1) ? a[i].y
                               : (kk == 2) ? a[i].z : a[i].w;
                const unsigned long long aa = pack2(av);
                ffma2(acc[i][0], aa, mp0.x);
                ffma2(acc[i][1], aa, mp0.y);
                ffma2(acc[i][2], aa, mp1.x);
                ffma2(acc[i][3], aa, mp1.y);
            }
        }
    }

    const float4 b0 = *reinterpret_cast<const float4*>(Wnode_b + tx * 8);
    const float4 b1 = *reinterpret_cast<const float4*>(Wnode_b + tx * 8 + 4);
    #pragma unroll
    for (int i = 0; i < 8; i++) {
        int grow = rb + ty * 8 + i;
        if (grow < n_node) {
            const float ws = g_wsum[grow];
            float2 a0 = unpack2(acc[i][0]);
            float2 a1 = unpack2(acc[i][1]);
            float2 a2 = unpack2(acc[i][2]);
            float2 a3 = unpack2(acc[i][3]);
            float* op = out + (size_t)grow * 64 + tx * 8;
            *reinterpret_cast<float4*>(op) =
                make_float4(a0.x + ws * b0.x, a0.y + ws * b0.y,
                            a1.x + ws * b0.z, a1.y + ws * b0.w);
            *reinterpret_cast<float4*>(op + 4) =
                make_float4(a2.x + ws * b1.x, a2.y + ws * b1.y,
                            a3.x + ws * b1.z, a3.y + ws * b1.w);
        }
    }
}

// ---------------------------------------------------------------------------
// kernel_launch
// ---------------------------------------------------------------------------
extern "C" void kernel_launch(void* const* d_in, const int* in_sizes, int n_in,
                              void* d_out, int out_size)
{
    const float* hidden    = (const float*)d_in[0];
    const float* rela      = (const float*)d_in[1];
    const float* Ws        = (const float*)d_in[2];
    const float* Wr        = (const float*)d_in[3];
    const float* Wqr_w     = (const float*)d_in[4];
    const float* Wqr_b     = (const float*)d_in[5];
    const float* walpha_w  = (const float*)d_in[6];
    const float* walpha_b  = (const float*)d_in[7];
    const float* Wh        = (const float*)d_in[8];
    const float* attn_fc_w = (const float*)d_in[9];
    const float* attn_fc_b = (const float*)d_in[10];
    const float* Wnode_w   = (const float*)d_in[11];
    const float* Wnode_b   = (const float*)d_in[12];
    const int*   q_rel     = (const int*)d_in[14];
    const int*   edges     = (const int*)d_in[15];
    float*       out       = (float*)d_out;

    const int n_edge = in_sizes[15] / 6;
    const int n_node = in_sizes[16] / 2;
    const int nrel   = in_sizes[1] / 64;
    const int batch  = in_sizes[14];
    const int nb     = (n_node + SCAN_CHUNK - 1) / SCAN_CHUNK;

    static bool attr_set = false;
    if (!attr_set) {
        cudaFuncSetAttribute(k_gemm, cudaFuncAttributeMaxDynamicSharedMemorySize,
                             GEMM_SMEM);
        attr_set = true;
    }

    // small tables
    k_setup<<<32, 256>>>(Wh, Wnode_w, attn_fc_w, rela, Wr, Wqr_w, Wqr_b,
                         q_rel, nrel, batch);

    // init t + wsum + hist + scalars
    k_init<<<4096, 256>>>(n_node);

    // H5 precompute (must precede k_scatter)
    k_h5<<<2368, 256>>>(hidden, Ws, n_node);

    // counting sort of edges by obj (hist stages compact tuples; scatter
    // computes alpha inline and writes ONE packed int4 per edge)
    k_hist<<<(n_edge + 255) / 256, 256>>>(edges, n_edge);
    k_scan_block<<<nb, SCAN_TPB>>>(n_node);
    k_scan_top<<<1, NB_MAX>>>(nb);
    k_scan_add<<<(n_node + 256) / 256, 256>>>(n_node, n_edge);
    k_scatter<<<(n_edge + 255) / 256, 256>>>(walpha_w, walpha_b, n_edge);

    // segment max + s0/s1 epilogue (warp per node)
    k_edge2<<<2368, 256>>>(hidden, rela, n_node);

    // softmax statistics (max, then sum; exp not materialized)
    k_score<<<(n_edge + 255) / 256, 256>>>(attn_fc_b, n_edge);
    k_sum<<<(n_edge + 255) / 256, 256>>>(n_edge);

    // t/wsum accumulation (16 threads/edge, RED.128, exp inline)
    k_taccum<<<(n_edge * 16 + 255) / 256, 256>>>(n_edge);

    // final GEMM: out = t@M + wsum*b (plain stores)
    k_gemm<<<(n_node + GEMM_ROWS - 1) / GEMM_ROWS, 256, GEMM_SMEM>>>(
        n_node, Wnode_b, out);
}